// round 12
// baseline (speedup 1.0000x reference)
#include <cuda_runtime.h>
#include <cuda_bf16.h>
#include <math.h>
#include <stdint.h>

// Problem constants
#define Bb 2
#define Ss 1024
#define Ee 1024
#define Hh 16
#define DHd 64
#define Ll 6
#define Ff 4096
#define Vv 400
#define Tt (Bb*Ss)        // 2048 tokens
#define E3 (3*Ee)         // 3072
#define NVPAD 512

// ---------------- scratch (device globals; no runtime allocation) -------------
__device__ float g_x  [Tt * Ee];
__device__ float g_tmp[Tt * Ee];
__device__ float g_fin[Tt * Ee];

__device__ __nv_bfloat16 g_wq_hi[Ll * E3 * Ee], g_wq_lo[Ll * E3 * Ee];
__device__ __nv_bfloat16 g_wo_hi[Ll * Ee * Ee], g_wo_lo[Ll * Ee * Ee];
__device__ __nv_bfloat16 g_w1_hi[Ll * Ff * Ee], g_w1_lo[Ll * Ff * Ee];
__device__ __nv_bfloat16 g_w2_hi[Ll * Ee * Ff], g_w2_lo[Ll * Ee * Ff];
__device__ __nv_bfloat16 g_x_hi [Tt * Ee],  g_x_lo [Tt * Ee];
__device__ __nv_bfloat16 g_qkv_hi[Tt * E3], g_qkv_lo[Tt * E3];
__device__ __nv_bfloat16 g_c_hi [Tt * Ee],  g_c_lo [Tt * Ee];
__device__ __nv_bfloat16 g_h_hi [Tt * Ff],  g_h_lo [Tt * Ff];
__device__ __nv_bfloat16 g_gw_hi[NVPAD * Ee], g_gw_lo[NVPAD * Ee];
__device__ float g_gb[NVPAD];

// ---------------- PTX helpers (base sm_103 ONLY) --------------------------------
__device__ __forceinline__ uint32_t smem_u32(const void* p) {
    uint32_t a;
    asm("{ .reg .u64 t; cvta.to.shared.u64 t, %1; cvt.u32.u64 %0, t; }" : "=r"(a) : "l"(p));
    return a;
}
__device__ __forceinline__ void cpa16(uint32_t dst, const void* src) {
    asm volatile("cp.async.cg.shared.global [%0], [%1], 16;" :: "r"(dst), "l"(src) : "memory");
}
__device__ __forceinline__ void cpa_commit() {
    asm volatile("cp.async.commit_group;" ::: "memory");
}
__device__ __forceinline__ void ldsm4(uint32_t* r, uint32_t addr) {
    asm volatile("ldmatrix.sync.aligned.m8n8.x4.shared.b16 {%0,%1,%2,%3}, [%4];"
                 : "=r"(r[0]), "=r"(r[1]), "=r"(r[2]), "=r"(r[3]) : "r"(addr));
}
__device__ __forceinline__ void ldsm4t(uint32_t* r, uint32_t addr) {
    asm volatile("ldmatrix.sync.aligned.m8n8.x4.trans.shared.b16 {%0,%1,%2,%3}, [%4];"
                 : "=r"(r[0]), "=r"(r[1]), "=r"(r[2]), "=r"(r[3]) : "r"(addr));
}
__device__ __forceinline__ void mma16816(float* c, const uint32_t* a, const uint32_t* b) {
    asm volatile(
        "mma.sync.aligned.m16n8k16.row.col.f32.bf16.bf16.f32 "
        "{%0,%1,%2,%3}, {%4,%5,%6,%7}, {%8,%9}, {%0,%1,%2,%3};"
        : "+f"(c[0]), "+f"(c[1]), "+f"(c[2]), "+f"(c[3])
        : "r"(a[0]), "r"(a[1]), "r"(a[2]), "r"(a[3]), "r"(b[0]), "r"(b[1]));
}
__device__ __forceinline__ void mma16816b(float* c, const uint32_t* a, uint32_t b0, uint32_t b1) {
    asm volatile(
        "mma.sync.aligned.m16n8k16.row.col.f32.bf16.bf16.f32 "
        "{%0,%1,%2,%3}, {%4,%5,%6,%7}, {%8,%9}, {%0,%1,%2,%3};"
        : "+f"(c[0]), "+f"(c[1]), "+f"(c[2]), "+f"(c[3])
        : "r"(a[0]), "r"(a[1]), "r"(a[2]), "r"(a[3]), "r"(b0), "r"(b1));
}
__device__ __forceinline__ float gelu_exact(float v) {
    return 0.5f * v * (1.0f + erff(v * 0.70710678118654752f));
}
__device__ __forceinline__ void packsplit2(float a, float b, uint32_t& hi, uint32_t& lo) {
    __nv_bfloat16 ah = __float2bfloat16(a), bh = __float2bfloat16(b);
    __nv_bfloat16 al = __float2bfloat16(a - __bfloat162float(ah));
    __nv_bfloat16 bl = __float2bfloat16(b - __bfloat162float(bh));
    hi = (uint32_t)__bfloat16_as_ushort(ah) | ((uint32_t)__bfloat16_as_ushort(bh) << 16);
    lo = (uint32_t)__bfloat16_as_ushort(al) | ((uint32_t)__bfloat16_as_ushort(bl) << 16);
}

// ---------------- fp32 -> bf16 hi/lo split (weights, one pass) ------------------
__global__ void split4_kernel(const float* __restrict__ x,
                              __nv_bfloat16* __restrict__ hi,
                              __nv_bfloat16* __restrict__ lo, int n4) {
    int i = blockIdx.x * blockDim.x + threadIdx.x;
    if (i >= n4) return;
    float4 v = ((const float4*)x)[i];
    uint32_t h0, l0, h1, l1;
    packsplit2(v.x, v.y, h0, l0);
    packsplit2(v.z, v.w, h1, l1);
    ((uint2*)hi)[i] = make_uint2(h0, h1);
    ((uint2*)lo)[i] = make_uint2(l0, l1);
}
__global__ void head_split_kernel(const float* __restrict__ gw,
                                  __nv_bfloat16* __restrict__ hi,
                                  __nv_bfloat16* __restrict__ lo) {
    int i = blockIdx.x * blockDim.x + threadIdx.x;
    int row = (i * 4) >> 10;
    float4 v = make_float4(0.f, 0.f, 0.f, 0.f);
    if (row < Vv) v = ((const float4*)gw)[i];
    uint32_t h0, l0, h1, l1;
    packsplit2(v.x, v.y, h0, l0);
    packsplit2(v.z, v.w, h1, l1);
    ((uint2*)hi)[i] = make_uint2(h0, h1);
    ((uint2*)lo)[i] = make_uint2(l0, l1);
}
__global__ void head_bias_kernel(const float* __restrict__ gb, float* __restrict__ out) {
    int i = blockIdx.x * blockDim.x + threadIdx.x;
    if (i < NVPAD) out[i] = (i < Vv) ? gb[i] : 0.f;
}

// ---------------- tensor-core GEMM via mma.sync (bf16x3, templated N-tile) -------
// NT = 128 or 64. Tile 128 x NT x 32, 256 threads (8 warps 2x4), 2-stage, 2 CTA/SM.
#define SROWB 80
#define PLANEB (128 * SROWB)        // A plane (128 rows)

template<int NT>
__device__ __forceinline__ void load_stage(uint32_t dst,
        const __nv_bfloat16* __restrict__ Ahi, const __nv_bfloat16* __restrict__ Alo,
        const __nv_bfloat16* __restrict__ Bhi, const __nv_bfloat16* __restrict__ Blo,
        int bm, int bn, int K, int kt, int tid) {
    constexpr int BPLANE = NT * SROWB;
    // A planes: 2 planes x 128 rows x 4 chunks = 1024 chunks
    #pragma unroll
    for (int c = 0; c < 4; c++) {
        int plane = c >> 1;
        int rem = (c & 1) * 256 + tid;
        int row = rem >> 2;
        int cc  = rem & 3;
        const __nv_bfloat16* src = (plane ? Alo : Ahi) + (size_t)(bm + row) * K + kt * 32 + cc * 8;
        cpa16(dst + plane * PLANEB + row * SROWB + cc * 16, src);
    }
    // B planes: 2 planes x NT rows x 4 chunks
    constexpr int BITER = (2 * NT * 4) / 256;
    #pragma unroll
    for (int c = 0; c < BITER; c++) {
        int idx = c * 256 + tid;
        int plane = idx / (NT * 4);
        int rem = idx - plane * (NT * 4);
        int row = rem >> 2;
        int cc  = rem & 3;
        const __nv_bfloat16* src = (plane ? Blo : Bhi) + (size_t)(bn + row) * K + kt * 32 + cc * 8;
        cpa16(dst + 2 * PLANEB + plane * BPLANE + row * SROWB + cc * 16, src);
    }
    cpa_commit();
}

template<int NT>
__global__ __launch_bounds__(256, 2)
void gemm_mma_kernel(const __nv_bfloat16* __restrict__ Ahi,
                     const __nv_bfloat16* __restrict__ Alo,
                     const __nv_bfloat16* __restrict__ Bhi,
                     const __nv_bfloat16* __restrict__ Blo,
                     const float* __restrict__ bias,
                     const float* __restrict__ addf,
                     float* __restrict__ Cf,
                     __nv_bfloat16* __restrict__ Chi,
                     __nv_bfloat16* __restrict__ Clo,
                     int M, int K, int act, int ldC, int Nv) {
    constexpr int BPLANE = NT * SROWB;
    constexpr int STAGE  = 2 * PLANEB + 2 * BPLANE;
    constexpr int P  = NT / 64;     // 16-row B groups per warp
    constexpr int JW = 2 * P;       // n8 fragments per warp
    extern __shared__ __align__(16) char smem[];
    uint32_t sb = smem_u32(smem);
    int tid = threadIdx.x, wid = tid >> 5, lane = tid & 31;
    int bm = blockIdx.y << 7, bn = blockIdx.x * NT;
    int warp_m = (wid >> 2) * 64;
    int warp_n = (wid & 3) * (NT / 4);

    float acc[4][JW][4];
    #pragma unroll
    for (int i = 0; i < 4; i++)
        #pragma unroll
        for (int j = 0; j < JW; j++)
            #pragma unroll
            for (int k = 0; k < 4; k++) acc[i][j][k] = 0.f;

    const int KT = K >> 5;
    load_stage<NT>(sb,         Ahi, Alo, Bhi, Blo, bm, bn, K, 0, tid);
    load_stage<NT>(sb + STAGE, Ahi, Alo, Bhi, Blo, bm, bn, K, 1, tid);

    int a_row = warp_m + (lane & 15);
    int a_koff = (lane >> 4) << 4;
    int b_row = warp_n + (lane & 7) + ((lane >> 4) << 3);
    int b_koff = ((lane >> 3) & 1) << 4;

    for (int kt = 0; kt < KT; kt++) {
        if (kt + 1 < KT) asm volatile("cp.async.wait_group 1;" ::: "memory");
        else             asm volatile("cp.async.wait_group 0;" ::: "memory");
        __syncthreads();

        uint32_t stage = sb + (kt & 1) * STAGE;
        #pragma unroll
        for (int ks = 0; ks < 2; ks++) {
            int kb = ks * 32;
            uint32_t ah[4][4], al[4][4], bh[P][4], bl[P][4];
            uint32_t a_addr = stage + a_row * SROWB + kb + a_koff;
            #pragma unroll
            for (int mt = 0; mt < 4; mt++) {
                ldsm4(ah[mt], a_addr + mt * 16 * SROWB);
                ldsm4(al[mt], a_addr + PLANEB + mt * 16 * SROWB);
            }
            uint32_t b_addr = stage + 2 * PLANEB + b_row * SROWB + kb + b_koff;
            #pragma unroll
            for (int p = 0; p < P; p++) {
                ldsm4(bh[p], b_addr + p * 16 * SROWB);
                ldsm4(bl[p], b_addr + BPLANE + p * 16 * SROWB);
            }
            #pragma unroll
            for (int mt = 0; mt < 4; mt++) {
                #pragma unroll
                for (int j = 0; j < JW; j++) {
                    int p = j >> 1, o = (j & 1) * 2;
                    mma16816(acc[mt][j], ah[mt], &bh[p][o]);
                    mma16816(acc[mt][j], ah[mt], &bl[p][o]);
                    mma16816(acc[mt][j], al[mt], &bh[p][o]);
                }
            }
        }
        __syncthreads();
        if (kt + 2 < KT)
            load_stage<NT>(sb + (kt & 1) * STAGE, Ahi, Alo, Bhi, Blo, bm, bn, K, kt + 2, tid);
    }

    int r0 = bm + warp_m + (lane >> 2);
    int c0 = bn + warp_n + (lane & 3) * 2;
    #pragma unroll
    for (int j = 0; j < JW; j++) {
        int col = c0 + j * 8;
        if (col >= Nv) continue;
        float b0 = __ldg(bias + col), b1 = __ldg(bias + col + 1);
        #pragma unroll
        for (int mt = 0; mt < 4; mt++) {
            int row = r0 + mt * 16;
            float v0 = acc[mt][j][0] + b0, v1 = acc[mt][j][1] + b1;
            float v2 = acc[mt][j][2] + b0, v3 = acc[mt][j][3] + b1;
            if (act) { v0 = gelu_exact(v0); v1 = gelu_exact(v1);
                       v2 = gelu_exact(v2); v3 = gelu_exact(v3); }
            if (addf) {
                float2 a0 = *(const float2*)(addf + (size_t)row * ldC + col);
                float2 a1 = *(const float2*)(addf + (size_t)(row + 8) * ldC + col);
                v0 += a0.x; v1 += a0.y; v2 += a1.x; v3 += a1.y;
            }
            if (Cf) {
                *(float2*)(Cf + (size_t)row * ldC + col)       = make_float2(v0, v1);
                *(float2*)(Cf + (size_t)(row + 8) * ldC + col) = make_float2(v2, v3);
            }
            if (Chi) {
                uint32_t h01, l01, h23, l23;
                packsplit2(v0, v1, h01, l01);
                packsplit2(v2, v3, h23, l23);
                *reinterpret_cast<uint32_t*>(Chi + (size_t)row * ldC + col)       = h01;
                *reinterpret_cast<uint32_t*>(Clo + (size_t)row * ldC + col)       = l01;
                *reinterpret_cast<uint32_t*>(Chi + (size_t)(row + 8) * ldC + col) = h23;
                *reinterpret_cast<uint32_t*>(Clo + (size_t)(row + 8) * ldC + col) = l23;
            }
        }
    }
}

#define GEMM_SMEM128 (2 * (2 * PLANEB + 2 * 128 * SROWB))   // 81920
#define GEMM_SMEM64  (2 * (2 * PLANEB + 2 * 64 * SROWB))    // 61440

// ---------------- embedding (fp32 + hi/lo) --------------------------------------
__global__ void embed_kernel(const int* __restrict__ seq,
                             const int* __restrict__ map1,
                             const int* __restrict__ map2,
                             const float* __restrict__ emb,
                             const float* __restrict__ pos,
                             float* __restrict__ x,
                             __nv_bfloat16* __restrict__ xhi,
                             __nv_bfloat16* __restrict__ xlo) {
    int idx2 = blockIdx.x * blockDim.x + threadIdx.x;
    int idx = idx2 * 2;
    int t = idx >> 10;
    int e = idx & 1023;
    int s = t & 1023;
    int tok = seq[t];
    int m1 = map1[tok], m2 = map2[tok];
    float v0 = (emb[(size_t)m1 * Ee + e] + emb[(size_t)m2 * Ee + e]) * 16.0f
               + pos[(size_t)s * Ee + e];
    float v1 = (emb[(size_t)m1 * Ee + e + 1] + emb[(size_t)m2 * Ee + e + 1]) * 16.0f
               + pos[(size_t)s * Ee + e + 1];
    *(float2*)(x + idx) = make_float2(v0, v1);
    uint32_t h, l;
    packsplit2(v0, v1, h, l);
    *reinterpret_cast<uint32_t*>(xhi + idx) = h;
    *reinterpret_cast<uint32_t*>(xlo + idx) = l;
}

// ---------------- LayerNorm ------------------------------------------------------
__global__ void add_ln_kernel(const float* __restrict__ x,
                              const float* __restrict__ r,
                              const float* __restrict__ w,
                              const float* __restrict__ b,
                              float* __restrict__ out,
                              __nv_bfloat16* __restrict__ ohi,
                              __nv_bfloat16* __restrict__ olo) {
    int t = blockIdx.x;
    const float* xr = x + (size_t)t * Ee;
    const float* rr = r ? (r + (size_t)t * Ee) : nullptr;
    float vals[4];
    float s = 0.f, ss = 0.f;
    #pragma unroll
    for (int u = 0; u < 4; u++) {
        int e = threadIdx.x + u * 256;
        float v = xr[e];
        if (rr) v += rr[e];
        vals[u] = v;
        s += v; ss += v * v;
    }
    #pragma unroll
    for (int o = 16; o > 0; o >>= 1) {
        s  += __shfl_down_sync(0xffffffffu, s,  o);
        ss += __shfl_down_sync(0xffffffffu, ss, o);
    }
    __shared__ float sm[8], sm2[8], tot[2];
    int warp = threadIdx.x >> 5, lane = threadIdx.x & 31;
    if (lane == 0) { sm[warp] = s; sm2[warp] = ss; }
    __syncthreads();
    if (threadIdx.x == 0) {
        float S = 0.f, SS = 0.f;
        #pragma unroll
        for (int i = 0; i < 8; i++) { S += sm[i]; SS += sm2[i]; }
        tot[0] = S; tot[1] = SS;
    }
    __syncthreads();
    float mean = tot[0] * (1.0f / Ee);
    float var  = tot[1] * (1.0f / Ee) - mean * mean;
    float inv  = rsqrtf(var + 1e-5f);
    float* orow = out + (size_t)t * Ee;
    #pragma unroll
    for (int u = 0; u < 4; u++) {
        int e = threadIdx.x + u * 256;
        float v = (vals[u] - mean) * inv * w[e] + b[e];
        orow[e] = v;
        if (ohi) {
            __nv_bfloat16 h = __float2bfloat16(v);
            ohi[(size_t)t * Ee + e] = h;
            olo[(size_t)t * Ee + e] = __float2bfloat16(v - __bfloat162float(h));
        }
    }
}

// ---------------- mma.sync flash attention (bf16 hi/lo x3) -----------------------
#define FSROW 144
#define FPLANE (64 * FSROW)
#define FQ_OFF 0
#define FST_OFF (2 * FPLANE)
#define FDCOL_OFF (FST_OFF + 8 * FPLANE)
#define FPAD_OFF (FDCOL_OFF + 4096)
#define FLASH_SMEM (FPAD_OFF + 512)

__device__ __forceinline__ void flash_load_kv(uint32_t sb,
        const __nv_bfloat16* __restrict__ qkv_hi, const __nv_bfloat16* __restrict__ qkv_lo,
        int* __restrict__ padf, const int* __restrict__ seq,
        size_t tokbase, int j0, int buf, int h, int tid) {
    uint32_t base = sb + FST_OFF + buf * 4 * FPLANE;
    #pragma unroll
    for (int it = 0; it < 16; it++) {
        int idx = it * 128 + tid;
        int plane = idx >> 9;
        int rem = idx & 511;
        int row = rem >> 3, ch = rem & 7;
        const __nv_bfloat16* pb = (plane & 1) ? qkv_lo : qkv_hi;
        int eoff = (plane < 2) ? Ee : 2 * Ee;
        const __nv_bfloat16* src = pb + (tokbase + j0 + row) * (size_t)E3 + eoff + h * 64 + ch * 8;
        cpa16(base + plane * FPLANE + row * FSROW + ch * 16, src);
    }
    if (tid < 64) padf[buf * 64 + tid] = (seq[tokbase + j0 + tid] == 0);
}

__global__ __launch_bounds__(128)
void flash_mma_kernel(const __nv_bfloat16* __restrict__ qkv_hi,
                      const __nv_bfloat16* __restrict__ qkv_lo,
                      const float* __restrict__ dist_emb,
                      const int* __restrict__ seq,
                      __nv_bfloat16* __restrict__ ctx_hi,
                      __nv_bfloat16* __restrict__ ctx_lo) {
    extern __shared__ __align__(16) char fsm[];
    uint32_t sb = smem_u32(fsm);
    float* dcol = (float*)(fsm + FDCOL_OFF);
    int*   padf = (int*)(fsm + FPAD_OFF);

    int bh = blockIdx.y, bq = bh >> 4, h = bh & 15;
    int qt = gridDim.x - 1 - blockIdx.x;
    int i0q = qt * 64;
    int nt = qt + 1;
    int tid = threadIdx.x, wid = tid >> 5, lane = tid & 31;
    size_t tokbase = (size_t)bq * Ss;

    for (int e = tid; e < Ss; e += 128) dcol[e] = dist_emb[e * Hh + h];

    #pragma unroll
    for (int it = 0; it < 8; it++) {
        int idx = it * 128 + tid;
        int plane = idx >> 9;
        int rem = idx & 511;
        int row = rem >> 3, ch = rem & 7;
        const __nv_bfloat16* src = (plane ? qkv_lo : qkv_hi)
            + (tokbase + i0q + row) * (size_t)E3 + h * 64 + ch * 8;
        cpa16(sb + FQ_OFF + plane * FPLANE + row * FSROW + ch * 16, src);
    }
    flash_load_kv(sb, qkv_hi, qkv_lo, padf, seq, tokbase, 0, 0, h, tid);
    cpa_commit();
    if (nt > 1) { flash_load_kv(sb, qkv_hi, qkv_lo, padf, seq, tokbase, 64, 1, h, tid); cpa_commit(); }

    uint32_t qh[4][4], ql[4][4];
    float o[8][4];
    #pragma unroll
    for (int j = 0; j < 8; j++)
        #pragma unroll
        for (int r = 0; r < 4; r++) o[j][r] = 0.f;
    float m0 = -1e30f, m1 = -1e30f, l0 = 0.f, l1 = 0.f;

    for (int t = 0; t < nt; t++) {
        if (t < nt - 1) asm volatile("cp.async.wait_group 1;" ::: "memory");
        else            asm volatile("cp.async.wait_group 0;" ::: "memory");
        __syncthreads();
        if (t == 0) {
            #pragma unroll
            for (int kk = 0; kk < 4; kk++) {
                uint32_t addr = sb + FQ_OFF + (wid * 16 + (lane & 15)) * FSROW
                                + kk * 32 + (lane >> 4) * 16;
                ldsm4(qh[kk], addr);
                ldsm4(ql[kk], addr + FPLANE);
            }
        }
        int buf = t & 1;
        uint32_t kbase = sb + FST_OFF + buf * 4 * FPLANE;

        float s[8][4];
        #pragma unroll
        for (int j = 0; j < 8; j++)
            #pragma unroll
            for (int r = 0; r < 4; r++) s[j][r] = 0.f;
        #pragma unroll
        for (int kk = 0; kk < 4; kk++) {
            #pragma unroll
            for (int g = 0; g < 4; g++) {
                uint32_t kh[4], kl[4];
                uint32_t addr = kbase + (g * 16 + (lane & 15)) * FSROW
                                + kk * 32 + (lane >> 4) * 16;
                ldsm4(kh, addr);
                ldsm4(kl, addr + FPLANE);
                mma16816b(s[2*g],   qh[kk], kh[0], kh[2]);
                mma16816b(s[2*g],   qh[kk], kl[0], kl[2]);
                mma16816b(s[2*g],   ql[kk], kh[0], kh[2]);
                mma16816b(s[2*g+1], qh[kk], kh[1], kh[3]);
                mma16816b(s[2*g+1], qh[kk], kl[1], kl[3]);
                mma16816b(s[2*g+1], ql[kk], kh[1], kh[3]);
            }
        }
        int j0 = t * 64;
        int dbase = (i0q - j0) + wid * 16 + (lane >> 2);
        #pragma unroll
        for (int j = 0; j < 8; j++) {
            #pragma unroll
            for (int r = 0; r < 4; r++) {
                int col = j * 8 + (lane & 3) * 2 + (r & 1);
                int d = dbase + ((r & 2) << 2) - col;
                bool ok = (d >= 0) && (padf[buf * 64 + col] == 0);
                s[j][r] = ok ? s[j][r] * 0.125f + dcol[d] : -1e30f;
            }
        }
        float rm0 = -1e30f, rm1 = -1e30f;
        #pragma unroll
        for (int j = 0; j < 8; j++) {
            rm0 = fmaxf(rm0, fmaxf(s[j][0], s[j][1]));
            rm1 = fmaxf(rm1, fmaxf(s[j][2], s[j][3]));
        }
        rm0 = fmaxf(rm0, __shfl_xor_sync(0xffffffffu, rm0, 1));
        rm0 = fmaxf(rm0, __shfl_xor_sync(0xffffffffu, rm0, 2));
        rm1 = fmaxf(rm1, __shfl_xor_sync(0xffffffffu, rm1, 1));
        rm1 = fmaxf(rm1, __shfl_xor_sync(0xffffffffu, rm1, 2));
        float mn0 = fmaxf(m0, rm0), mn1 = fmaxf(m1, rm1);
        float c0 = __expf(m0 - mn0), c1 = __expf(m1 - mn1);
        m0 = mn0; m1 = mn1;
        float ps0 = 0.f, ps1 = 0.f;
        #pragma unroll
        for (int j = 0; j < 8; j++) {
            s[j][0] = __expf(s[j][0] - mn0); ps0 += s[j][0];
            s[j][1] = __expf(s[j][1] - mn0); ps0 += s[j][1];
            s[j][2] = __expf(s[j][2] - mn1); ps1 += s[j][2];
            s[j][3] = __expf(s[j][3] - mn1); ps1 += s[j][3];
        }
        l0 = l0 * c0 + ps0;
        l1 = l1 * c1 + ps1;
        #pragma unroll
        for (int j = 0; j < 8; j++) {
            o[j][0] *= c0; o[j][1] *= c0; o[j][2] *= c1; o[j][3] *= c1;
        }
        uint32_t ph[4][4], pl[4][4];
        #pragma unroll
        for (int u = 0; u < 4; u++) {
            packsplit2(s[2*u][0],   s[2*u][1],   ph[u][0], pl[u][0]);
            packsplit2(s[2*u][2],   s[2*u][3],   ph[u][1], pl[u][1]);
            packsplit2(s[2*u+1][0], s[2*u+1][1], ph[u][2], pl[u][2]);
            packsplit2(s[2*u+1][2], s[2*u+1][3], ph[u][3], pl[u][3]);
        }
        uint32_t vbase = kbase + 2 * FPLANE;
        #pragma unroll
        for (int u = 0; u < 4; u++) {
            #pragma unroll
            for (int g = 0; g < 4; g++) {
                uint32_t vh[4], vl[4];
                uint32_t addr = vbase + (u * 16 + (lane & 7) + ((lane >> 3) & 1) * 8) * FSROW
                                + g * 32 + (lane >> 4) * 16;
                ldsm4t(vh, addr);
                ldsm4t(vl, addr + FPLANE);
                mma16816b(o[2*g],   ph[u], vh[0], vh[1]);
                mma16816b(o[2*g],   ph[u], vl[0], vl[1]);
                mma16816b(o[2*g],   pl[u], vh[0], vh[1]);
                mma16816b(o[2*g+1], ph[u], vh[2], vh[3]);
                mma16816b(o[2*g+1], ph[u], vl[2], vl[3]);
                mma16816b(o[2*g+1], pl[u], vh[2], vh[3]);
            }
        }
        __syncthreads();
        if (t + 2 < nt) {
            flash_load_kv(sb, qkv_hi, qkv_lo, padf, seq, tokbase, (t + 2) * 64, buf, h, tid);
            cpa_commit();
        }
    }

    l0 += __shfl_xor_sync(0xffffffffu, l0, 1);
    l0 += __shfl_xor_sync(0xffffffffu, l0, 2);
    l1 += __shfl_xor_sync(0xffffffffu, l1, 1);
    l1 += __shfl_xor_sync(0xffffffffu, l1, 2);
    float inv0 = 1.0f / l0, inv1 = 1.0f / l1;

    size_t tok0 = tokbase + i0q + wid * 16 + (lane >> 2);
    int colb = h * 64 + (lane & 3) * 2;
    #pragma unroll
    for (int j = 0; j < 8; j++) {
        float v0 = o[j][0] * inv0, v1 = o[j][1] * inv0;
        float v2 = o[j][2] * inv1, v3 = o[j][3] * inv1;
        uint32_t h01, l01, h23, l23;
        packsplit2(v0, v1, h01, l01);
        packsplit2(v2, v3, h23, l23);
        *reinterpret_cast<uint32_t*>(ctx_hi + tok0 * Ee + colb + j * 8)       = h01;
        *reinterpret_cast<uint32_t*>(ctx_lo + tok0 * Ee + colb + j * 8)       = l01;
        *reinterpret_cast<uint32_t*>(ctx_hi + (tok0 + 8) * Ee + colb + j * 8) = h23;
        *reinterpret_cast<uint32_t*>(ctx_lo + (tok0 + 8) * Ee + colb + j * 8) = l23;
    }
}

// ---------------- host orchestration -------------------------------------------
static inline void split_launch(const float* src, __nv_bfloat16* hi, __nv_bfloat16* lo, int n) {
    int n4 = n >> 2;
    split4_kernel<<<(n4 + 255) / 256, 256>>>(src, hi, lo, n4);
}

extern "C" void kernel_launch(void* const* d_in, const int* in_sizes, int n_in,
                              void* d_out, int out_size) {
    const int*   seq        = (const int*)  d_in[0];
    const int*   map1       = (const int*)  d_in[1];
    const int*   map2       = (const int*)  d_in[2];
    const float* emb        = (const float*)d_in[3];
    const float* pos_emb    = (const float*)d_in[4];
    const float* dist_emb   = (const float*)d_in[5];
    const float* in_proj_w  = (const float*)d_in[6];
    const float* in_proj_b  = (const float*)d_in[7];
    const float* out_proj_w = (const float*)d_in[8];
    const float* out_proj_b = (const float*)d_in[9];
    const float* lin1_w     = (const float*)d_in[10];
    const float* lin1_b     = (const float*)d_in[11];
    const float* lin2_w     = (const float*)d_in[12];
    const float* lin2_b     = (const float*)d_in[13];
    const float* ln1_w      = (const float*)d_in[14];
    const float* ln1_b      = (const float*)d_in[15];
    const float* ln2_w      = (const float*)d_in[16];
    const float* ln2_b      = (const float*)d_in[17];
    const float* fnorm_w    = (const float*)d_in[18];
    const float* fnorm_b    = (const float*)d_in[19];
    const float* gen_w      = (const float*)d_in[20];
    const float* gen_b      = (const float*)d_in[21];
    float* out = (float*)d_out;

    float *x, *tmpp, *finp, *gbp;
    cudaGetSymbolAddress((void**)&x,    g_x);
    cudaGetSymbolAddress((void**)&tmpp, g_tmp);
    cudaGetSymbolAddress((void**)&finp, g_fin);
    cudaGetSymbolAddress((void**)&gbp,  g_gb);
    __nv_bfloat16 *wq_hi, *wq_lo, *wo_hi, *wo_lo, *w1_hi, *w1_lo, *w2_hi, *w2_lo;
    __nv_bfloat16 *x_hi, *x_lo, *qkv_hi, *qkv_lo, *c_hi, *c_lo, *h_hi, *h_lo, *gw_hi, *gw_lo;
    cudaGetSymbolAddress((void**)&wq_hi, g_wq_hi); cudaGetSymbolAddress((void**)&wq_lo, g_wq_lo);
    cudaGetSymbolAddress((void**)&wo_hi, g_wo_hi); cudaGetSymbolAddress((void**)&wo_lo, g_wo_lo);
    cudaGetSymbolAddress((void**)&w1_hi, g_w1_hi); cudaGetSymbolAddress((void**)&w1_lo, g_w1_lo);
    cudaGetSymbolAddress((void**)&w2_hi, g_w2_hi); cudaGetSymbolAddress((void**)&w2_lo, g_w2_lo);
    cudaGetSymbolAddress((void**)&x_hi,  g_x_hi);  cudaGetSymbolAddress((void**)&x_lo,  g_x_lo);
    cudaGetSymbolAddress((void**)&qkv_hi, g_qkv_hi); cudaGetSymbolAddress((void**)&qkv_lo, g_qkv_lo);
    cudaGetSymbolAddress((void**)&c_hi,  g_c_hi);  cudaGetSymbolAddress((void**)&c_lo,  g_c_lo);
    cudaGetSymbolAddress((void**)&h_hi,  g_h_hi);  cudaGetSymbolAddress((void**)&h_lo,  g_h_lo);
    cudaGetSymbolAddress((void**)&gw_hi, g_gw_hi); cudaGetSymbolAddress((void**)&gw_lo, g_gw_lo);

    cudaFuncSetAttribute(gemm_mma_kernel<128>, cudaFuncAttributeMaxDynamicSharedMemorySize, GEMM_SMEM128);
    cudaFuncSetAttribute(gemm_mma_kernel<64>,  cudaFuncAttributeMaxDynamicSharedMemorySize, GEMM_SMEM64);
    cudaFuncSetAttribute(flash_mma_kernel, cudaFuncAttributeMaxDynamicSharedMemorySize, FLASH_SMEM);

    // weight hi/lo split (one pass)
    split_launch(in_proj_w,  wq_hi, wq_lo, Ll * E3 * Ee);
    split_launch(out_proj_w, wo_hi, wo_lo, Ll * Ee * Ee);
    split_launch(lin1_w,     w1_hi, w1_lo, Ll * Ff * Ee);
    split_launch(lin2_w,     w2_hi, w2_lo, Ll * Ee * Ff);
    head_split_kernel<<<(NVPAD * Ee / 4) / 256, 256>>>(gen_w, gw_hi, gw_lo);
    head_bias_kernel<<<2, 256>>>(gen_b, gbp);

    // embedding
    embed_kernel<<<(Tt * Ee / 2) / 256, 256>>>(seq, map1, map2, emb, pos_emb, x, x_hi, x_lo);

    for (int l = 0; l < Ll; l++) {
        // qkv = x @ Wq^T + b -> hi/lo   (NT=128: 24x16=384 CTAs)
        gemm_mma_kernel<128><<<dim3(E3 / 128, Tt / 128), 256, GEMM_SMEM128>>>(
            x_hi, x_lo, wq_hi + (size_t)l * E3 * Ee, wq_lo + (size_t)l * E3 * Ee,
            in_proj_b + (size_t)l * E3, nullptr, nullptr, qkv_hi, qkv_lo, Tt, Ee, 0, E3, E3);
        // attention -> ctx hi/lo
        flash_mma_kernel<<<dim3(Ss / 64, Bb * Hh), 128, FLASH_SMEM>>>(
            qkv_hi, qkv_lo, dist_emb, seq, c_hi, c_lo);
        // tmp = ctx @ Wo^T + b + x   (NT=64: 16x16=256 CTAs)
        gemm_mma_kernel<64><<<dim3(Ee / 64, Tt / 128), 256, GEMM_SMEM64>>>(
            c_hi, c_lo, wo_hi + (size_t)l * Ee * Ee, wo_lo + (size_t)l * Ee * Ee,
            out_proj_b + (size_t)l * Ee, x, tmpp, nullptr, nullptr, Tt, Ee, 0, Ee, Ee);
        // x = LN(tmp)
        add_ln_kernel<<<Tt, 256>>>(tmpp, nullptr, ln1_w + (size_t)l * Ee, ln1_b + (size_t)l * Ee,
                                   x, x_hi, x_lo);
        // h = gelu(x @ W1^T + b) -> hi/lo   (NT=128: 32x16=512 CTAs)
        gemm_mma_kernel<128><<<dim3(Ff / 128, Tt / 128), 256, GEMM_SMEM128>>>(
            x_hi, x_lo, w1_hi + (size_t)l * Ff * Ee, w1_lo + (size_t)l * Ff * Ee,
            lin1_b + (size_t)l * Ff, nullptr, nullptr, h_hi, h_lo, Tt, Ee, 1, Ff, Ff);
        // tmp = h @ W2^T + b + x   (NT=64: 16x16=256 CTAs)
        gemm_mma_kernel<64><<<dim3(Ee / 64, Tt / 128), 256, GEMM_SMEM64>>>(
            h_hi, h_lo, w2_hi + (size_t)l * Ee * Ff, w2_lo + (size_t)l * Ee * Ff,
            lin2_b + (size_t)l * Ee, x, tmpp, nullptr, nullptr, Tt, Ff, 0, Ee, Ee);
        // x = LN(tmp)
        add_ln_kernel<<<Tt, 256>>>(tmpp, nullptr, ln2_w + (size_t)l * Ee, ln2_b + (size_t)l * Ee,
                                   x, x_hi, x_lo);
    }

    // final norm -> fp32 + hi/lo
    add_ln_kernel<<<Tt, 256>>>(x, nullptr, fnorm_w, fnorm_b, finp, x_hi, x_lo);
    // logits = xn @ gen_w^T + gen_b   (NT=64: 8x16=128 CTAs, guarded to 400)
    gemm_mma_kernel<64><<<dim3(NVPAD / 64, Tt / 128), 256, GEMM_SMEM64>>>(
        x_hi, x_lo, gw_hi, gw_lo, gbp, nullptr, out, nullptr, nullptr, Tt, Ee, 0, Vv, Vv);
}

// round 13
// speedup vs baseline: 1.0923x; 1.0923x over previous
#include <cuda_runtime.h>
#include <cuda_bf16.h>
#include <math.h>
#include <stdint.h>

// Problem constants
#define Bb 2
#define Ss 1024
#define Ee 1024
#define Hh 16
#define DHd 64
#define Ll 6
#define Ff 4096
#define Vv 400
#define Tt (Bb*Ss)        // 2048 tokens
#define E3 (3*Ee)         // 3072
#define NVPAD 512

// ---------------- scratch (device globals; no runtime allocation) -------------
__device__ float g_x  [Tt * Ee];
__device__ float g_tmp[2 * Tt * Ee];   // split-K partials (z=0 carries bias+residual)
__device__ float g_fin[Tt * Ee];

__device__ __nv_bfloat16 g_wq_hi[Ll * E3 * Ee], g_wq_lo[Ll * E3 * Ee];
__device__ __nv_bfloat16 g_wo_hi[Ll * Ee * Ee], g_wo_lo[Ll * Ee * Ee];
__device__ __nv_bfloat16 g_w1_hi[Ll * Ff * Ee], g_w1_lo[Ll * Ff * Ee];
__device__ __nv_bfloat16 g_w2_hi[Ll * Ee * Ff], g_w2_lo[Ll * Ee * Ff];
__device__ __nv_bfloat16 g_x_hi [Tt * Ee],  g_x_lo [Tt * Ee];
__device__ __nv_bfloat16 g_qkv_hi[Tt * E3], g_qkv_lo[Tt * E3];
__device__ __nv_bfloat16 g_c_hi [Tt * Ee],  g_c_lo [Tt * Ee];
__device__ __nv_bfloat16 g_h_hi [Tt * Ff],  g_h_lo [Tt * Ff];
__device__ __nv_bfloat16 g_gw_hi[NVPAD * Ee], g_gw_lo[NVPAD * Ee];
__device__ float g_gb[NVPAD];

// ---------------- PTX helpers (base sm_103 ONLY) --------------------------------
__device__ __forceinline__ uint32_t smem_u32(const void* p) {
    uint32_t a;
    asm("{ .reg .u64 t; cvta.to.shared.u64 t, %1; cvt.u32.u64 %0, t; }" : "=r"(a) : "l"(p));
    return a;
}
__device__ __forceinline__ void cpa16(uint32_t dst, const void* src) {
    asm volatile("cp.async.cg.shared.global [%0], [%1], 16;" :: "r"(dst), "l"(src) : "memory");
}
__device__ __forceinline__ void cpa_commit() {
    asm volatile("cp.async.commit_group;" ::: "memory");
}
__device__ __forceinline__ void ldsm4(uint32_t* r, uint32_t addr) {
    asm volatile("ldmatrix.sync.aligned.m8n8.x4.shared.b16 {%0,%1,%2,%3}, [%4];"
                 : "=r"(r[0]), "=r"(r[1]), "=r"(r[2]), "=r"(r[3]) : "r"(addr));
}
__device__ __forceinline__ void ldsm4t(uint32_t* r, uint32_t addr) {
    asm volatile("ldmatrix.sync.aligned.m8n8.x4.trans.shared.b16 {%0,%1,%2,%3}, [%4];"
                 : "=r"(r[0]), "=r"(r[1]), "=r"(r[2]), "=r"(r[3]) : "r"(addr));
}
__device__ __forceinline__ void mma16816(float* c, const uint32_t* a, const uint32_t* b) {
    asm volatile(
        "mma.sync.aligned.m16n8k16.row.col.f32.bf16.bf16.f32 "
        "{%0,%1,%2,%3}, {%4,%5,%6,%7}, {%8,%9}, {%0,%1,%2,%3};"
        : "+f"(c[0]), "+f"(c[1]), "+f"(c[2]), "+f"(c[3])
        : "r"(a[0]), "r"(a[1]), "r"(a[2]), "r"(a[3]), "r"(b[0]), "r"(b[1]));
}
__device__ __forceinline__ void mma16816b(float* c, const uint32_t* a, uint32_t b0, uint32_t b1) {
    asm volatile(
        "mma.sync.aligned.m16n8k16.row.col.f32.bf16.bf16.f32 "
        "{%0,%1,%2,%3}, {%4,%5,%6,%7}, {%8,%9}, {%0,%1,%2,%3};"
        : "+f"(c[0]), "+f"(c[1]), "+f"(c[2]), "+f"(c[3])
        : "r"(a[0]), "r"(a[1]), "r"(a[2]), "r"(a[3]), "r"(b0), "r"(b1));
}
__device__ __forceinline__ float gelu_exact(float v) {
    return 0.5f * v * (1.0f + erff(v * 0.70710678118654752f));
}
__device__ __forceinline__ void packsplit2(float a, float b, uint32_t& hi, uint32_t& lo) {
    __nv_bfloat16 ah = __float2bfloat16(a), bh = __float2bfloat16(b);
    __nv_bfloat16 al = __float2bfloat16(a - __bfloat162float(ah));
    __nv_bfloat16 bl = __float2bfloat16(b - __bfloat162float(bh));
    hi = (uint32_t)__bfloat16_as_ushort(ah) | ((uint32_t)__bfloat16_as_ushort(bh) << 16);
    lo = (uint32_t)__bfloat16_as_ushort(al) | ((uint32_t)__bfloat16_as_ushort(bl) << 16);
}

// ---------------- fp32 -> bf16 hi/lo split (weights, one pass) ------------------
__global__ void split4_kernel(const float* __restrict__ x,
                              __nv_bfloat16* __restrict__ hi,
                              __nv_bfloat16* __restrict__ lo, int n4) {
    int i = blockIdx.x * blockDim.x + threadIdx.x;
    if (i >= n4) return;
    float4 v = ((const float4*)x)[i];
    uint32_t h0, l0, h1, l1;
    packsplit2(v.x, v.y, h0, l0);
    packsplit2(v.z, v.w, h1, l1);
    ((uint2*)hi)[i] = make_uint2(h0, h1);
    ((uint2*)lo)[i] = make_uint2(l0, l1);
}
__global__ void head_split_kernel(const float* __restrict__ gw,
                                  __nv_bfloat16* __restrict__ hi,
                                  __nv_bfloat16* __restrict__ lo) {
    int i = blockIdx.x * blockDim.x + threadIdx.x;
    int row = (i * 4) >> 10;
    float4 v = make_float4(0.f, 0.f, 0.f, 0.f);
    if (row < Vv) v = ((const float4*)gw)[i];
    uint32_t h0, l0, h1, l1;
    packsplit2(v.x, v.y, h0, l0);
    packsplit2(v.z, v.w, h1, l1);
    ((uint2*)hi)[i] = make_uint2(h0, h1);
    ((uint2*)lo)[i] = make_uint2(l0, l1);
}
__global__ void head_bias_kernel(const float* __restrict__ gb, float* __restrict__ out) {
    int i = blockIdx.x * blockDim.x + threadIdx.x;
    if (i < NVPAD) out[i] = (i < Vv) ? gb[i] : 0.f;
}

// ---------------- tensor-core GEMM via mma.sync (bf16x3, 128x128x32, split-K) ----
// grid.z = K-splits. Split z computes Ksub columns starting at z*Ksub, writes
// Cf + z*M*ldC. Bias/addf applied only on z==0. Chi/Clo only valid for 1 split.
#define SROWB 80
#define PLANEB (128 * SROWB)
#define STAGEB (4 * PLANEB)        // 40960 B
#define GEMM_SMEM (2 * STAGEB)     // 81920 -> 2 CTAs/SM

__device__ __forceinline__ void load_stage(uint32_t dst,
        const __nv_bfloat16* __restrict__ Ahi, const __nv_bfloat16* __restrict__ Alo,
        const __nv_bfloat16* __restrict__ Bhi, const __nv_bfloat16* __restrict__ Blo,
        int bm, int bn, int ldK, int koff, int kt, int tid) {
    const __nv_bfloat16* srcs[4] = {Ahi, Alo, Bhi, Blo};
    #pragma unroll
    for (int c = 0; c < 8; c++) {
        int plane = c >> 1;
        int rem = (c & 1) * 256 + tid;
        int row = rem >> 2;
        int cc  = rem & 3;
        int base_row = (plane < 2 ? bm : bn) + row;
        const __nv_bfloat16* src = srcs[plane] + (size_t)base_row * ldK + koff + kt * 32 + cc * 8;
        cpa16(dst + plane * PLANEB + row * SROWB + cc * 16, src);
    }
    cpa_commit();
}

__global__ __launch_bounds__(256, 2)
void gemm_mma_kernel(const __nv_bfloat16* __restrict__ Ahi,
                     const __nv_bfloat16* __restrict__ Alo,
                     const __nv_bfloat16* __restrict__ Bhi,
                     const __nv_bfloat16* __restrict__ Blo,
                     const float* __restrict__ bias,
                     const float* __restrict__ addf,
                     float* __restrict__ Cf,
                     __nv_bfloat16* __restrict__ Chi,
                     __nv_bfloat16* __restrict__ Clo,
                     int M, int ldK, int Ksub, int act, int ldC, int Nv) {
    extern __shared__ __align__(16) char smem[];
    uint32_t sb = smem_u32(smem);
    int tid = threadIdx.x, wid = tid >> 5, lane = tid & 31;
    int bm = blockIdx.y << 7, bn = blockIdx.x << 7;
    int z = blockIdx.z;
    int koff = z * Ksub;
    int warp_m = (wid >> 2) * 64;
    int warp_n = (wid & 3) * 32;

    float acc[4][4][4];
    #pragma unroll
    for (int i = 0; i < 4; i++)
        #pragma unroll
        for (int j = 0; j < 4; j++)
            #pragma unroll
            for (int k = 0; k < 4; k++) acc[i][j][k] = 0.f;

    const int KT = Ksub >> 5;
    load_stage(sb,          Ahi, Alo, Bhi, Blo, bm, bn, ldK, koff, 0, tid);
    load_stage(sb + STAGEB, Ahi, Alo, Bhi, Blo, bm, bn, ldK, koff, 1, tid);

    int a_row = warp_m + (lane & 15);
    int a_koff = (lane >> 4) << 4;
    int b_row = warp_n + (lane & 7) + ((lane >> 4) << 3);
    int b_koff = ((lane >> 3) & 1) << 4;

    for (int kt = 0; kt < KT; kt++) {
        if (kt + 1 < KT) asm volatile("cp.async.wait_group 1;" ::: "memory");
        else             asm volatile("cp.async.wait_group 0;" ::: "memory");
        __syncthreads();

        uint32_t stage = sb + (kt & 1) * STAGEB;
        #pragma unroll
        for (int ks = 0; ks < 2; ks++) {
            int kb = ks * 32;
            uint32_t ah[4][4], al[4][4], bh[2][4], bl[2][4];
            uint32_t a_addr = stage + a_row * SROWB + kb + a_koff;
            #pragma unroll
            for (int mt = 0; mt < 4; mt++) {
                ldsm4(ah[mt], a_addr + mt * 16 * SROWB);
                ldsm4(al[mt], a_addr + PLANEB + mt * 16 * SROWB);
            }
            uint32_t b_addr = stage + 2 * PLANEB + b_row * SROWB + kb + b_koff;
            #pragma unroll
            for (int p = 0; p < 2; p++) {
                ldsm4(bh[p], b_addr + p * 16 * SROWB);
                ldsm4(bl[p], b_addr + PLANEB + p * 16 * SROWB);
            }
            #pragma unroll
            for (int mt = 0; mt < 4; mt++) {
                #pragma unroll
                for (int j = 0; j < 4; j++) {
                    int p = j >> 1, o = (j & 1) * 2;
                    mma16816(acc[mt][j], ah[mt], &bh[p][o]);
                    mma16816(acc[mt][j], ah[mt], &bl[p][o]);
                    mma16816(acc[mt][j], al[mt], &bh[p][o]);
                }
            }
        }
        __syncthreads();
        if (kt + 2 < KT)
            load_stage(sb + (kt & 1) * STAGEB, Ahi, Alo, Bhi, Blo, bm, bn, ldK, koff, kt + 2, tid);
    }

    float* Cfz = Cf ? Cf + (size_t)z * M * ldC : nullptr;
    int r0 = bm + warp_m + (lane >> 2);
    int c0 = bn + warp_n + (lane & 3) * 2;
    #pragma unroll
    for (int j = 0; j < 4; j++) {
        int col = c0 + j * 8;
        if (col >= Nv) continue;
        float b0 = 0.f, b1 = 0.f;
        if (z == 0) { b0 = __ldg(bias + col); b1 = __ldg(bias + col + 1); }
        #pragma unroll
        for (int mt = 0; mt < 4; mt++) {
            int row = r0 + mt * 16;
            float v0 = acc[mt][j][0] + b0, v1 = acc[mt][j][1] + b1;
            float v2 = acc[mt][j][2] + b0, v3 = acc[mt][j][3] + b1;
            if (act) { v0 = gelu_exact(v0); v1 = gelu_exact(v1);
                       v2 = gelu_exact(v2); v3 = gelu_exact(v3); }
            if (addf && z == 0) {
                float2 a0 = *(const float2*)(addf + (size_t)row * ldC + col);
                float2 a1 = *(const float2*)(addf + (size_t)(row + 8) * ldC + col);
                v0 += a0.x; v1 += a0.y; v2 += a1.x; v3 += a1.y;
            }
            if (Cfz) {
                *(float2*)(Cfz + (size_t)row * ldC + col)       = make_float2(v0, v1);
                *(float2*)(Cfz + (size_t)(row + 8) * ldC + col) = make_float2(v2, v3);
            }
            if (Chi) {
                uint32_t h01, l01, h23, l23;
                packsplit2(v0, v1, h01, l01);
                packsplit2(v2, v3, h23, l23);
                *reinterpret_cast<uint32_t*>(Chi + (size_t)row * ldC + col)       = h01;
                *reinterpret_cast<uint32_t*>(Clo + (size_t)row * ldC + col)       = l01;
                *reinterpret_cast<uint32_t*>(Chi + (size_t)(row + 8) * ldC + col) = h23;
                *reinterpret_cast<uint32_t*>(Clo + (size_t)(row + 8) * ldC + col) = l23;
            }
        }
    }
}

// ---------------- embedding (fp32 + hi/lo) --------------------------------------
__global__ void embed_kernel(const int* __restrict__ seq,
                             const int* __restrict__ map1,
                             const int* __restrict__ map2,
                             const float* __restrict__ emb,
                             const float* __restrict__ pos,
                             float* __restrict__ x,
                             __nv_bfloat16* __restrict__ xhi,
                             __nv_bfloat16* __restrict__ xlo) {
    int idx2 = blockIdx.x * blockDim.x + threadIdx.x;
    int idx = idx2 * 2;
    int t = idx >> 10;
    int e = idx & 1023;
    int s = t & 1023;
    int tok = seq[t];
    int m1 = map1[tok], m2 = map2[tok];
    float v0 = (emb[(size_t)m1 * Ee + e] + emb[(size_t)m2 * Ee + e]) * 16.0f
               + pos[(size_t)s * Ee + e];
    float v1 = (emb[(size_t)m1 * Ee + e + 1] + emb[(size_t)m2 * Ee + e + 1]) * 16.0f
               + pos[(size_t)s * Ee + e + 1];
    *(float2*)(x + idx) = make_float2(v0, v1);
    uint32_t h, l;
    packsplit2(v0, v1, h, l);
    *reinterpret_cast<uint32_t*>(xhi + idx) = h;
    *reinterpret_cast<uint32_t*>(xlo + idx) = l;
}

// ---------------- LayerNorm (x + optional r addend = split-K reduction) ----------
__global__ void add_ln_kernel(const float* __restrict__ x,
                              const float* __restrict__ r,
                              const float* __restrict__ w,
                              const float* __restrict__ b,
                              float* __restrict__ out,
                              __nv_bfloat16* __restrict__ ohi,
                              __nv_bfloat16* __restrict__ olo) {
    int t = blockIdx.x;
    const float* xr = x + (size_t)t * Ee;
    const float* rr = r ? (r + (size_t)t * Ee) : nullptr;
    float vals[4];
    float s = 0.f, ss = 0.f;
    #pragma unroll
    for (int u = 0; u < 4; u++) {
        int e = threadIdx.x + u * 256;
        float v = xr[e];
        if (rr) v += rr[e];
        vals[u] = v;
        s += v; ss += v * v;
    }
    #pragma unroll
    for (int o = 16; o > 0; o >>= 1) {
        s  += __shfl_down_sync(0xffffffffu, s,  o);
        ss += __shfl_down_sync(0xffffffffu, ss, o);
    }
    __shared__ float sm[8], sm2[8], tot[2];
    int warp = threadIdx.x >> 5, lane = threadIdx.x & 31;
    if (lane == 0) { sm[warp] = s; sm2[warp] = ss; }
    __syncthreads();
    if (threadIdx.x == 0) {
        float S = 0.f, SS = 0.f;
        #pragma unroll
        for (int i = 0; i < 8; i++) { S += sm[i]; SS += sm2[i]; }
        tot[0] = S; tot[1] = SS;
    }
    __syncthreads();
    float mean = tot[0] * (1.0f / Ee);
    float var  = tot[1] * (1.0f / Ee) - mean * mean;
    float inv  = rsqrtf(var + 1e-5f);
    float* orow = out + (size_t)t * Ee;
    #pragma unroll
    for (int u = 0; u < 4; u++) {
        int e = threadIdx.x + u * 256;
        float v = (vals[u] - mean) * inv * w[e] + b[e];
        orow[e] = v;
        if (ohi) {
            __nv_bfloat16 h = __float2bfloat16(v);
            ohi[(size_t)t * Ee + e] = h;
            olo[(size_t)t * Ee + e] = __float2bfloat16(v - __bfloat162float(h));
        }
    }
}

// ---------------- mma.sync flash attention (bf16 hi/lo x3) -----------------------
#define FSROW 144
#define FPLANE (64 * FSROW)
#define FQ_OFF 0
#define FST_OFF (2 * FPLANE)
#define FDCOL_OFF (FST_OFF + 8 * FPLANE)
#define FPAD_OFF (FDCOL_OFF + 4096)
#define FLASH_SMEM (FPAD_OFF + 512)

__device__ __forceinline__ void flash_load_kv(uint32_t sb,
        const __nv_bfloat16* __restrict__ qkv_hi, const __nv_bfloat16* __restrict__ qkv_lo,
        int* __restrict__ padf, const int* __restrict__ seq,
        size_t tokbase, int j0, int buf, int h, int tid) {
    uint32_t base = sb + FST_OFF + buf * 4 * FPLANE;
    #pragma unroll
    for (int it = 0; it < 16; it++) {
        int idx = it * 128 + tid;
        int plane = idx >> 9;
        int rem = idx & 511;
        int row = rem >> 3, ch = rem & 7;
        const __nv_bfloat16* pb = (plane & 1) ? qkv_lo : qkv_hi;
        int eoff = (plane < 2) ? Ee : 2 * Ee;
        const __nv_bfloat16* src = pb + (tokbase + j0 + row) * (size_t)E3 + eoff + h * 64 + ch * 8;
        cpa16(base + plane * FPLANE + row * FSROW + ch * 16, src);
    }
    if (tid < 64) padf[buf * 64 + tid] = (seq[tokbase + j0 + tid] == 0);
}

__global__ __launch_bounds__(128)
void flash_mma_kernel(const __nv_bfloat16* __restrict__ qkv_hi,
                      const __nv_bfloat16* __restrict__ qkv_lo,
                      const float* __restrict__ dist_emb,
                      const int* __restrict__ seq,
                      __nv_bfloat16* __restrict__ ctx_hi,
                      __nv_bfloat16* __restrict__ ctx_lo) {
    extern __shared__ __align__(16) char fsm[];
    uint32_t sb = smem_u32(fsm);
    float* dcol = (float*)(fsm + FDCOL_OFF);
    int*   padf = (int*)(fsm + FPAD_OFF);

    int bh = blockIdx.y, bq = bh >> 4, h = bh & 15;
    int qt = gridDim.x - 1 - blockIdx.x;
    int i0q = qt * 64;
    int nt = qt + 1;
    int tid = threadIdx.x, wid = tid >> 5, lane = tid & 31;
    size_t tokbase = (size_t)bq * Ss;

    for (int e = tid; e < Ss; e += 128) dcol[e] = dist_emb[e * Hh + h];

    #pragma unroll
    for (int it = 0; it < 8; it++) {
        int idx = it * 128 + tid;
        int plane = idx >> 9;
        int rem = idx & 511;
        int row = rem >> 3, ch = rem & 7;
        const __nv_bfloat16* src = (plane ? qkv_lo : qkv_hi)
            + (tokbase + i0q + row) * (size_t)E3 + h * 64 + ch * 8;
        cpa16(sb + FQ_OFF + plane * FPLANE + row * FSROW + ch * 16, src);
    }
    flash_load_kv(sb, qkv_hi, qkv_lo, padf, seq, tokbase, 0, 0, h, tid);
    cpa_commit();
    if (nt > 1) { flash_load_kv(sb, qkv_hi, qkv_lo, padf, seq, tokbase, 64, 1, h, tid); cpa_commit(); }

    uint32_t qh[4][4], ql[4][4];
    float o[8][4];
    #pragma unroll
    for (int j = 0; j < 8; j++)
        #pragma unroll
        for (int r = 0; r < 4; r++) o[j][r] = 0.f;
    float m0 = -1e30f, m1 = -1e30f, l0 = 0.f, l1 = 0.f;

    for (int t = 0; t < nt; t++) {
        if (t < nt - 1) asm volatile("cp.async.wait_group 1;" ::: "memory");
        else            asm volatile("cp.async.wait_group 0;" ::: "memory");
        __syncthreads();
        if (t == 0) {
            #pragma unroll
            for (int kk = 0; kk < 4; kk++) {
                uint32_t addr = sb + FQ_OFF + (wid * 16 + (lane & 15)) * FSROW
                                + kk * 32 + (lane >> 4) * 16;
                ldsm4(qh[kk], addr);
                ldsm4(ql[kk], addr + FPLANE);
            }
        }
        int buf = t & 1;
        uint32_t kbase = sb + FST_OFF + buf * 4 * FPLANE;

        float s[8][4];
        #pragma unroll
        for (int j = 0; j < 8; j++)
            #pragma unroll
            for (int r = 0; r < 4; r++) s[j][r] = 0.f;
        #pragma unroll
        for (int kk = 0; kk < 4; kk++) {
            #pragma unroll
            for (int g = 0; g < 4; g++) {
                uint32_t kh[4], kl[4];
                uint32_t addr = kbase + (g * 16 + (lane & 15)) * FSROW
                                + kk * 32 + (lane >> 4) * 16;
                ldsm4(kh, addr);
                ldsm4(kl, addr + FPLANE);
                mma16816b(s[2*g],   qh[kk], kh[0], kh[2]);
                mma16816b(s[2*g],   qh[kk], kl[0], kl[2]);
                mma16816b(s[2*g],   ql[kk], kh[0], kh[2]);
                mma16816b(s[2*g+1], qh[kk], kh[1], kh[3]);
                mma16816b(s[2*g+1], qh[kk], kl[1], kl[3]);
                mma16816b(s[2*g+1], ql[kk], kh[1], kh[3]);
            }
        }
        int j0 = t * 64;
        int dbase = (i0q - j0) + wid * 16 + (lane >> 2);
        #pragma unroll
        for (int j = 0; j < 8; j++) {
            #pragma unroll
            for (int r = 0; r < 4; r++) {
                int col = j * 8 + (lane & 3) * 2 + (r & 1);
                int d = dbase + ((r & 2) << 2) - col;
                bool ok = (d >= 0) && (padf[buf * 64 + col] == 0);
                s[j][r] = ok ? s[j][r] * 0.125f + dcol[d] : -1e30f;
            }
        }
        float rm0 = -1e30f, rm1 = -1e30f;
        #pragma unroll
        for (int j = 0; j < 8; j++) {
            rm0 = fmaxf(rm0, fmaxf(s[j][0], s[j][1]));
            rm1 = fmaxf(rm1, fmaxf(s[j][2], s[j][3]));
        }
        rm0 = fmaxf(rm0, __shfl_xor_sync(0xffffffffu, rm0, 1));
        rm0 = fmaxf(rm0, __shfl_xor_sync(0xffffffffu, rm0, 2));
        rm1 = fmaxf(rm1, __shfl_xor_sync(0xffffffffu, rm1, 1));
        rm1 = fmaxf(rm1, __shfl_xor_sync(0xffffffffu, rm1, 2));
        float mn0 = fmaxf(m0, rm0), mn1 = fmaxf(m1, rm1);
        float c0 = __expf(m0 - mn0), c1 = __expf(m1 - mn1);
        m0 = mn0; m1 = mn1;
        float ps0 = 0.f, ps1 = 0.f;
        #pragma unroll
        for (int j = 0; j < 8; j++) {
            s[j][0] = __expf(s[j][0] - mn0); ps0 += s[j][0];
            s[j][1] = __expf(s[j][1] - mn0); ps0 += s[j][1];
            s[j][2] = __expf(s[j][2] - mn1); ps1 += s[j][2];
            s[j][3] = __expf(s[j][3] - mn1); ps1 += s[j][3];
        }
        l0 = l0 * c0 + ps0;
        l1 = l1 * c1 + ps1;
        #pragma unroll
        for (int j = 0; j < 8; j++) {
            o[j][0] *= c0; o[j][1] *= c0; o[j][2] *= c1; o[j][3] *= c1;
        }
        uint32_t ph[4][4], pl[4][4];
        #pragma unroll
        for (int u = 0; u < 4; u++) {
            packsplit2(s[2*u][0],   s[2*u][1],   ph[u][0], pl[u][0]);
            packsplit2(s[2*u][2],   s[2*u][3],   ph[u][1], pl[u][1]);
            packsplit2(s[2*u+1][0], s[2*u+1][1], ph[u][2], pl[u][2]);
            packsplit2(s[2*u+1][2], s[2*u+1][3], ph[u][3], pl[u][3]);
        }
        uint32_t vbase = kbase + 2 * FPLANE;
        #pragma unroll
        for (int u = 0; u < 4; u++) {
            #pragma unroll
            for (int g = 0; g < 4; g++) {
                uint32_t vh[4], vl[4];
                uint32_t addr = vbase + (u * 16 + (lane & 7) + ((lane >> 3) & 1) * 8) * FSROW
                                + g * 32 + (lane >> 4) * 16;
                ldsm4t(vh, addr);
                ldsm4t(vl, addr + FPLANE);
                mma16816b(o[2*g],   ph[u], vh[0], vh[1]);
                mma16816b(o[2*g],   ph[u], vl[0], vl[1]);
                mma16816b(o[2*g],   pl[u], vh[0], vh[1]);
                mma16816b(o[2*g+1], ph[u], vh[2], vh[3]);
                mma16816b(o[2*g+1], ph[u], vl[2], vl[3]);
                mma16816b(o[2*g+1], pl[u], vh[2], vh[3]);
            }
        }
        __syncthreads();
        if (t + 2 < nt) {
            flash_load_kv(sb, qkv_hi, qkv_lo, padf, seq, tokbase, (t + 2) * 64, buf, h, tid);
            cpa_commit();
        }
    }

    l0 += __shfl_xor_sync(0xffffffffu, l0, 1);
    l0 += __shfl_xor_sync(0xffffffffu, l0, 2);
    l1 += __shfl_xor_sync(0xffffffffu, l1, 1);
    l1 += __shfl_xor_sync(0xffffffffu, l1, 2);
    float inv0 = 1.0f / l0, inv1 = 1.0f / l1;

    size_t tok0 = tokbase + i0q + wid * 16 + (lane >> 2);
    int colb = h * 64 + (lane & 3) * 2;
    #pragma unroll
    for (int j = 0; j < 8; j++) {
        float v0 = o[j][0] * inv0, v1 = o[j][1] * inv0;
        float v2 = o[j][2] * inv1, v3 = o[j][3] * inv1;
        uint32_t h01, l01, h23, l23;
        packsplit2(v0, v1, h01, l01);
        packsplit2(v2, v3, h23, l23);
        *reinterpret_cast<uint32_t*>(ctx_hi + tok0 * Ee + colb + j * 8)       = h01;
        *reinterpret_cast<uint32_t*>(ctx_lo + tok0 * Ee + colb + j * 8)       = l01;
        *reinterpret_cast<uint32_t*>(ctx_hi + (tok0 + 8) * Ee + colb + j * 8) = h23;
        *reinterpret_cast<uint32_t*>(ctx_lo + (tok0 + 8) * Ee + colb + j * 8) = l23;
    }
}

// ---------------- host orchestration -------------------------------------------
static inline void split_launch(const float* src, __nv_bfloat16* hi, __nv_bfloat16* lo, int n) {
    int n4 = n >> 2;
    split4_kernel<<<(n4 + 255) / 256, 256>>>(src, hi, lo, n4);
}

extern "C" void kernel_launch(void* const* d_in, const int* in_sizes, int n_in,
                              void* d_out, int out_size) {
    const int*   seq        = (const int*)  d_in[0];
    const int*   map1       = (const int*)  d_in[1];
    const int*   map2       = (const int*)  d_in[2];
    const float* emb        = (const float*)d_in[3];
    const float* pos_emb    = (const float*)d_in[4];
    const float* dist_emb   = (const float*)d_in[5];
    const float* in_proj_w  = (const float*)d_in[6];
    const float* in_proj_b  = (const float*)d_in[7];
    const float* out_proj_w = (const float*)d_in[8];
    const float* out_proj_b = (const float*)d_in[9];
    const float* lin1_w     = (const float*)d_in[10];
    const float* lin1_b     = (const float*)d_in[11];
    const float* lin2_w     = (const float*)d_in[12];
    const float* lin2_b     = (const float*)d_in[13];
    const float* ln1_w      = (const float*)d_in[14];
    const float* ln1_b      = (const float*)d_in[15];
    const float* ln2_w      = (const float*)d_in[16];
    const float* ln2_b      = (const float*)d_in[17];
    const float* fnorm_w    = (const float*)d_in[18];
    const float* fnorm_b    = (const float*)d_in[19];
    const float* gen_w      = (const float*)d_in[20];
    const float* gen_b      = (const float*)d_in[21];
    float* out = (float*)d_out;

    float *x, *tmpp, *finp, *gbp;
    cudaGetSymbolAddress((void**)&x,    g_x);
    cudaGetSymbolAddress((void**)&tmpp, g_tmp);
    cudaGetSymbolAddress((void**)&finp, g_fin);
    cudaGetSymbolAddress((void**)&gbp,  g_gb);
    __nv_bfloat16 *wq_hi, *wq_lo, *wo_hi, *wo_lo, *w1_hi, *w1_lo, *w2_hi, *w2_lo;
    __nv_bfloat16 *x_hi, *x_lo, *qkv_hi, *qkv_lo, *c_hi, *c_lo, *h_hi, *h_lo, *gw_hi, *gw_lo;
    cudaGetSymbolAddress((void**)&wq_hi, g_wq_hi); cudaGetSymbolAddress((void**)&wq_lo, g_wq_lo);
    cudaGetSymbolAddress((void**)&wo_hi, g_wo_hi); cudaGetSymbolAddress((void**)&wo_lo, g_wo_lo);
    cudaGetSymbolAddress((void**)&w1_hi, g_w1_hi); cudaGetSymbolAddress((void**)&w1_lo, g_w1_lo);
    cudaGetSymbolAddress((void**)&w2_hi, g_w2_hi); cudaGetSymbolAddress((void**)&w2_lo, g_w2_lo);
    cudaGetSymbolAddress((void**)&x_hi,  g_x_hi);  cudaGetSymbolAddress((void**)&x_lo,  g_x_lo);
    cudaGetSymbolAddress((void**)&qkv_hi, g_qkv_hi); cudaGetSymbolAddress((void**)&qkv_lo, g_qkv_lo);
    cudaGetSymbolAddress((void**)&c_hi,  g_c_hi);  cudaGetSymbolAddress((void**)&c_lo,  g_c_lo);
    cudaGetSymbolAddress((void**)&h_hi,  g_h_hi);  cudaGetSymbolAddress((void**)&h_lo,  g_h_lo);
    cudaGetSymbolAddress((void**)&gw_hi, g_gw_hi); cudaGetSymbolAddress((void**)&gw_lo, g_gw_lo);

    cudaFuncSetAttribute(gemm_mma_kernel, cudaFuncAttributeMaxDynamicSharedMemorySize, GEMM_SMEM);
    cudaFuncSetAttribute(flash_mma_kernel, cudaFuncAttributeMaxDynamicSharedMemorySize, FLASH_SMEM);

    // weight hi/lo split (one pass)
    split_launch(in_proj_w,  wq_hi, wq_lo, Ll * E3 * Ee);
    split_launch(out_proj_w, wo_hi, wo_lo, Ll * Ee * Ee);
    split_launch(lin1_w,     w1_hi, w1_lo, Ll * Ff * Ee);
    split_launch(lin2_w,     w2_hi, w2_lo, Ll * Ee * Ff);
    head_split_kernel<<<(NVPAD * Ee / 4) / 256, 256>>>(gen_w, gw_hi, gw_lo);
    head_bias_kernel<<<2, 256>>>(gen_b, gbp);

    // embedding
    embed_kernel<<<(Tt * Ee / 2) / 256, 256>>>(seq, map1, map2, emb, pos_emb, x, x_hi, x_lo);

    const size_t TE = (size_t)Tt * Ee;
    for (int l = 0; l < Ll; l++) {
        // qkv = x @ Wq^T + b -> hi/lo   (384 CTAs)
        gemm_mma_kernel<<<dim3(E3 / 128, Tt / 128, 1), 256, GEMM_SMEM>>>(
            x_hi, x_lo, wq_hi + (size_t)l * E3 * Ee, wq_lo + (size_t)l * E3 * Ee,
            in_proj_b + (size_t)l * E3, nullptr, nullptr, qkv_hi, qkv_lo,
            Tt, Ee, Ee, 0, E3, E3);
        // attention -> ctx hi/lo
        flash_mma_kernel<<<dim3(Ss / 64, Bb * Hh), 128, FLASH_SMEM>>>(
            qkv_hi, qkv_lo, dist_emb, seq, c_hi, c_lo);
        // tmp[z] = partial(ctx @ Wo^T); z0 += b + x   (split-K=2: 256 CTAs)
        gemm_mma_kernel<<<dim3(Ee / 128, Tt / 128, 2), 256, GEMM_SMEM>>>(
            c_hi, c_lo, wo_hi + (size_t)l * Ee * Ee, wo_lo + (size_t)l * Ee * Ee,
            out_proj_b + (size_t)l * Ee, x, tmpp, nullptr, nullptr,
            Tt, Ee, Ee / 2, 0, Ee, Ee);
        // x = LN(tmp0 + tmp1)
        add_ln_kernel<<<Tt, 256>>>(tmpp, tmpp + TE, ln1_w + (size_t)l * Ee, ln1_b + (size_t)l * Ee,
                                   x, x_hi, x_lo);
        // h = gelu(x @ W1^T + b) -> hi/lo   (512 CTAs)
        gemm_mma_kernel<<<dim3(Ff / 128, Tt / 128, 1), 256, GEMM_SMEM>>>(
            x_hi, x_lo, w1_hi + (size_t)l * Ff * Ee, w1_lo + (size_t)l * Ff * Ee,
            lin1_b + (size_t)l * Ff, nullptr, nullptr, h_hi, h_lo,
            Tt, Ee, Ee, 1, Ff, Ff);
        // tmp[z] = partial(h @ W2^T); z0 += b + x   (split-K=2: 256 CTAs)
        gemm_mma_kernel<<<dim3(Ee / 128, Tt / 128, 2), 256, GEMM_SMEM>>>(
            h_hi, h_lo, w2_hi + (size_t)l * Ee * Ff, w2_lo + (size_t)l * Ee * Ff,
            lin2_b + (size_t)l * Ee, x, tmpp, nullptr, nullptr,
            Tt, Ff, Ff / 2, 0, Ee, Ee);
        // x = LN(tmp0 + tmp1)
        add_ln_kernel<<<Tt, 256>>>(tmpp, tmpp + TE, ln2_w + (size_t)l * Ee, ln2_b + (size_t)l * Ee,
                                   x, x_hi, x_lo);
    }

    // final norm -> fp32 + hi/lo
    add_ln_kernel<<<Tt, 256>>>(x, nullptr, fnorm_w, fnorm_b, finp, x_hi, x_lo);
    // logits = xn @ gen_w^T + gen_b (padded N=512, guarded to 400)
    gemm_mma_kernel<<<dim3(NVPAD / 128, Tt / 128, 1), 256, GEMM_SMEM>>>(
        x_hi, x_lo, gw_hi, gw_lo, gbp, nullptr, out, nullptr, nullptr,
        Tt, Ee, Ee, 0, Vv, Vv);
}

// round 14
// speedup vs baseline: 1.1044x; 1.0111x over previous
#include <cuda_runtime.h>
#include <cuda_bf16.h>
#include <math.h>
#include <stdint.h>

// Problem constants
#define Bb 2
#define Ss 1024
#define Ee 1024
#define Hh 16
#define DHd 64
#define Ll 6
#define Ff 4096
#define Vv 400
#define Tt (Bb*Ss)        // 2048 tokens
#define E3 (3*Ee)         // 3072
#define NVPAD 512

// ---------------- scratch (device globals; no runtime allocation) -------------
__device__ float g_x  [Tt * Ee];
__device__ float g_tmp[2 * Tt * Ee];   // split-K partials (z=0 carries bias+residual)
__device__ float g_fin[Tt * Ee];

__device__ __nv_bfloat16 g_wq_hi[Ll * E3 * Ee], g_wq_lo[Ll * E3 * Ee];
__device__ __nv_bfloat16 g_wo_hi[Ll * Ee * Ee], g_wo_lo[Ll * Ee * Ee];
__device__ __nv_bfloat16 g_w1_hi[Ll * Ff * Ee], g_w1_lo[Ll * Ff * Ee];
__device__ __nv_bfloat16 g_w2_hi[Ll * Ee * Ff], g_w2_lo[Ll * Ee * Ff];
__device__ __nv_bfloat16 g_x_hi [Tt * Ee],  g_x_lo [Tt * Ee];
__device__ __nv_bfloat16 g_qkv_hi[Tt * E3], g_qkv_lo[Tt * E3];
__device__ __nv_bfloat16 g_c_hi [Tt * Ee],  g_c_lo [Tt * Ee];
__device__ __nv_bfloat16 g_h_hi [Tt * Ff],  g_h_lo [Tt * Ff];
__device__ __nv_bfloat16 g_gw_hi[NVPAD * Ee], g_gw_lo[NVPAD * Ee];
__device__ float g_gb[NVPAD];

// ---------------- PTX helpers (base sm_103 ONLY) --------------------------------
__device__ __forceinline__ uint32_t smem_u32(const void* p) {
    uint32_t a;
    asm("{ .reg .u64 t; cvta.to.shared.u64 t, %1; cvt.u32.u64 %0, t; }" : "=r"(a) : "l"(p));
    return a;
}
__device__ __forceinline__ void cpa16(uint32_t dst, const void* src) {
    asm volatile("cp.async.cg.shared.global [%0], [%1], 16;" :: "r"(dst), "l"(src) : "memory");
}
__device__ __forceinline__ void cpa_commit() {
    asm volatile("cp.async.commit_group;" ::: "memory");
}
__device__ __forceinline__ void ldsm4(uint32_t* r, uint32_t addr) {
    asm volatile("ldmatrix.sync.aligned.m8n8.x4.shared.b16 {%0,%1,%2,%3}, [%4];"
                 : "=r"(r[0]), "=r"(r[1]), "=r"(r[2]), "=r"(r[3]) : "r"(addr));
}
__device__ __forceinline__ void ldsm4t(uint32_t* r, uint32_t addr) {
    asm volatile("ldmatrix.sync.aligned.m8n8.x4.trans.shared.b16 {%0,%1,%2,%3}, [%4];"
                 : "=r"(r[0]), "=r"(r[1]), "=r"(r[2]), "=r"(r[3]) : "r"(addr));
}
__device__ __forceinline__ void mma16816(float* c, const uint32_t* a, const uint32_t* b) {
    asm volatile(
        "mma.sync.aligned.m16n8k16.row.col.f32.bf16.bf16.f32 "
        "{%0,%1,%2,%3}, {%4,%5,%6,%7}, {%8,%9}, {%0,%1,%2,%3};"
        : "+f"(c[0]), "+f"(c[1]), "+f"(c[2]), "+f"(c[3])
        : "r"(a[0]), "r"(a[1]), "r"(a[2]), "r"(a[3]), "r"(b[0]), "r"(b[1]));
}
__device__ __forceinline__ void mma16816b(float* c, const uint32_t* a, uint32_t b0, uint32_t b1) {
    asm volatile(
        "mma.sync.aligned.m16n8k16.row.col.f32.bf16.bf16.f32 "
        "{%0,%1,%2,%3}, {%4,%5,%6,%7}, {%8,%9}, {%0,%1,%2,%3};"
        : "+f"(c[0]), "+f"(c[1]), "+f"(c[2]), "+f"(c[3])
        : "r"(a[0]), "r"(a[1]), "r"(a[2]), "r"(a[3]), "r"(b0), "r"(b1));
}
__device__ __forceinline__ float gelu_exact(float v) {
    return 0.5f * v * (1.0f + erff(v * 0.70710678118654752f));
}
__device__ __forceinline__ void packsplit2(float a, float b, uint32_t& hi, uint32_t& lo) {
    __nv_bfloat16 ah = __float2bfloat16(a), bh = __float2bfloat16(b);
    __nv_bfloat16 al = __float2bfloat16(a - __bfloat162float(ah));
    __nv_bfloat16 bl = __float2bfloat16(b - __bfloat162float(bh));
    hi = (uint32_t)__bfloat16_as_ushort(ah) | ((uint32_t)__bfloat16_as_ushort(bh) << 16);
    lo = (uint32_t)__bfloat16_as_ushort(al) | ((uint32_t)__bfloat16_as_ushort(bl) << 16);
}

// ---------------- fp32 -> bf16 hi/lo split (weights) ----------------------------
__global__ void split4_kernel(const float* __restrict__ x,
                              __nv_bfloat16* __restrict__ hi,
                              __nv_bfloat16* __restrict__ lo, int n4) {
    int i = blockIdx.x * blockDim.x + threadIdx.x;
    if (i >= n4) return;
    float4 v = ((const float4*)x)[i];
    uint32_t h0, l0, h1, l1;
    packsplit2(v.x, v.y, h0, l0);
    packsplit2(v.z, v.w, h1, l1);
    ((uint2*)hi)[i] = make_uint2(h0, h1);
    ((uint2*)lo)[i] = make_uint2(l0, l1);
}
__global__ void head_split_kernel(const float* __restrict__ gw,
                                  __nv_bfloat16* __restrict__ hi,
                                  __nv_bfloat16* __restrict__ lo) {
    int i = blockIdx.x * blockDim.x + threadIdx.x;
    int row = (i * 4) >> 10;
    float4 v = make_float4(0.f, 0.f, 0.f, 0.f);
    if (row < Vv) v = ((const float4*)gw)[i];
    uint32_t h0, l0, h1, l1;
    packsplit2(v.x, v.y, h0, l0);
    packsplit2(v.z, v.w, h1, l1);
    ((uint2*)hi)[i] = make_uint2(h0, h1);
    ((uint2*)lo)[i] = make_uint2(l0, l1);
}
__global__ void head_bias_kernel(const float* __restrict__ gb, float* __restrict__ out) {
    int i = blockIdx.x * blockDim.x + threadIdx.x;
    if (i < NVPAD) out[i] = (i < Vv) ? gb[i] : 0.f;
}

// ---------------- tensor-core GEMM via mma.sync (bf16x3, 128x128x32, split-K) ----
#define SROWB 80
#define PLANEB (128 * SROWB)
#define STAGEB (4 * PLANEB)        // 40960 B
#define GEMM_SMEM (2 * STAGEB)     // 81920 -> 2 CTAs/SM

__device__ __forceinline__ void load_stage(uint32_t dst,
        const __nv_bfloat16* __restrict__ Ahi, const __nv_bfloat16* __restrict__ Alo,
        const __nv_bfloat16* __restrict__ Bhi, const __nv_bfloat16* __restrict__ Blo,
        int bm, int bn, int ldK, int koff, int kt, int tid) {
    const __nv_bfloat16* srcs[4] = {Ahi, Alo, Bhi, Blo};
    #pragma unroll
    for (int c = 0; c < 8; c++) {
        int plane = c >> 1;
        int rem = (c & 1) * 256 + tid;
        int row = rem >> 2;
        int cc  = rem & 3;
        int base_row = (plane < 2 ? bm : bn) + row;
        const __nv_bfloat16* src = srcs[plane] + (size_t)base_row * ldK + koff + kt * 32 + cc * 8;
        cpa16(dst + plane * PLANEB + row * SROWB + cc * 16, src);
    }
    cpa_commit();
}

__global__ __launch_bounds__(256, 2)
void gemm_mma_kernel(const __nv_bfloat16* __restrict__ Ahi,
                     const __nv_bfloat16* __restrict__ Alo,
                     const __nv_bfloat16* __restrict__ Bhi,
                     const __nv_bfloat16* __restrict__ Blo,
                     const float* __restrict__ bias,
                     const float* __restrict__ addf,
                     float* __restrict__ Cf,
                     __nv_bfloat16* __restrict__ Chi,
                     __nv_bfloat16* __restrict__ Clo,
                     int M, int ldK, int Ksub, int act, int ldC, int Nv) {
    extern __shared__ __align__(16) char smem[];
    uint32_t sb = smem_u32(smem);
    int tid = threadIdx.x, wid = tid >> 5, lane = tid & 31;
    int bm = blockIdx.y << 7, bn = blockIdx.x << 7;
    int z = blockIdx.z;
    int koff = z * Ksub;
    int warp_m = (wid >> 2) * 64;
    int warp_n = (wid & 3) * 32;

    float acc[4][4][4];
    #pragma unroll
    for (int i = 0; i < 4; i++)
        #pragma unroll
        for (int j = 0; j < 4; j++)
            #pragma unroll
            for (int k = 0; k < 4; k++) acc[i][j][k] = 0.f;

    const int KT = Ksub >> 5;
    load_stage(sb,          Ahi, Alo, Bhi, Blo, bm, bn, ldK, koff, 0, tid);
    load_stage(sb + STAGEB, Ahi, Alo, Bhi, Blo, bm, bn, ldK, koff, 1, tid);

    int a_row = warp_m + (lane & 15);
    int a_koff = (lane >> 4) << 4;
    int b_row = warp_n + (lane & 7) + ((lane >> 4) << 3);
    int b_koff = ((lane >> 3) & 1) << 4;

    for (int kt = 0; kt < KT; kt++) {
        if (kt + 1 < KT) asm volatile("cp.async.wait_group 1;" ::: "memory");
        else             asm volatile("cp.async.wait_group 0;" ::: "memory");
        __syncthreads();

        uint32_t stage = sb + (kt & 1) * STAGEB;
        #pragma unroll
        for (int ks = 0; ks < 2; ks++) {
            int kb = ks * 32;
            uint32_t ah[4][4], al[4][4], bh[2][4], bl[2][4];
            uint32_t a_addr = stage + a_row * SROWB + kb + a_koff;
            #pragma unroll
            for (int mt = 0; mt < 4; mt++) {
                ldsm4(ah[mt], a_addr + mt * 16 * SROWB);
                ldsm4(al[mt], a_addr + PLANEB + mt * 16 * SROWB);
            }
            uint32_t b_addr = stage + 2 * PLANEB + b_row * SROWB + kb + b_koff;
            #pragma unroll
            for (int p = 0; p < 2; p++) {
                ldsm4(bh[p], b_addr + p * 16 * SROWB);
                ldsm4(bl[p], b_addr + PLANEB + p * 16 * SROWB);
            }
            #pragma unroll
            for (int mt = 0; mt < 4; mt++) {
                #pragma unroll
                for (int j = 0; j < 4; j++) {
                    int p = j >> 1, o = (j & 1) * 2;
                    mma16816(acc[mt][j], ah[mt], &bh[p][o]);
                    mma16816(acc[mt][j], ah[mt], &bl[p][o]);
                    mma16816(acc[mt][j], al[mt], &bh[p][o]);
                }
            }
        }
        __syncthreads();
        if (kt + 2 < KT)
            load_stage(sb + (kt & 1) * STAGEB, Ahi, Alo, Bhi, Blo, bm, bn, ldK, koff, kt + 2, tid);
    }

    float* Cfz = Cf ? Cf + (size_t)z * M * ldC : nullptr;
    int r0 = bm + warp_m + (lane >> 2);
    int c0 = bn + warp_n + (lane & 3) * 2;
    #pragma unroll
    for (int j = 0; j < 4; j++) {
        int col = c0 + j * 8;
        if (col >= Nv) continue;
        float b0 = 0.f, b1 = 0.f;
        if (z == 0) { b0 = __ldg(bias + col); b1 = __ldg(bias + col + 1); }
        #pragma unroll
        for (int mt = 0; mt < 4; mt++) {
            int row = r0 + mt * 16;
            float v0 = acc[mt][j][0] + b0, v1 = acc[mt][j][1] + b1;
            float v2 = acc[mt][j][2] + b0, v3 = acc[mt][j][3] + b1;
            if (act) { v0 = gelu_exact(v0); v1 = gelu_exact(v1);
                       v2 = gelu_exact(v2); v3 = gelu_exact(v3); }
            if (addf && z == 0) {
                float2 a0 = *(const float2*)(addf + (size_t)row * ldC + col);
                float2 a1 = *(const float2*)(addf + (size_t)(row + 8) * ldC + col);
                v0 += a0.x; v1 += a0.y; v2 += a1.x; v3 += a1.y;
            }
            if (Cfz) {
                *(float2*)(Cfz + (size_t)row * ldC + col)       = make_float2(v0, v1);
                *(float2*)(Cfz + (size_t)(row + 8) * ldC + col) = make_float2(v2, v3);
            }
            if (Chi) {
                uint32_t h01, l01, h23, l23;
                packsplit2(v0, v1, h01, l01);
                packsplit2(v2, v3, h23, l23);
                *reinterpret_cast<uint32_t*>(Chi + (size_t)row * ldC + col)       = h01;
                *reinterpret_cast<uint32_t*>(Clo + (size_t)row * ldC + col)       = l01;
                *reinterpret_cast<uint32_t*>(Chi + (size_t)(row + 8) * ldC + col) = h23;
                *reinterpret_cast<uint32_t*>(Clo + (size_t)(row + 8) * ldC + col) = l23;
            }
        }
    }
}

// ---------------- embedding (fp32 + hi/lo) --------------------------------------
__global__ void embed_kernel(const int* __restrict__ seq,
                             const int* __restrict__ map1,
                             const int* __restrict__ map2,
                             const float* __restrict__ emb,
                             const float* __restrict__ pos,
                             float* __restrict__ x,
                             __nv_bfloat16* __restrict__ xhi,
                             __nv_bfloat16* __restrict__ xlo) {
    int idx2 = blockIdx.x * blockDim.x + threadIdx.x;
    int idx = idx2 * 2;
    int t = idx >> 10;
    int e = idx & 1023;
    int s = t & 1023;
    int tok = seq[t];
    int m1 = map1[tok], m2 = map2[tok];
    float v0 = (emb[(size_t)m1 * Ee + e] + emb[(size_t)m2 * Ee + e]) * 16.0f
               + pos[(size_t)s * Ee + e];
    float v1 = (emb[(size_t)m1 * Ee + e + 1] + emb[(size_t)m2 * Ee + e + 1]) * 16.0f
               + pos[(size_t)s * Ee + e + 1];
    *(float2*)(x + idx) = make_float2(v0, v1);
    uint32_t h, l;
    packsplit2(v0, v1, h, l);
    *reinterpret_cast<uint32_t*>(xhi + idx) = h;
    *reinterpret_cast<uint32_t*>(xlo + idx) = l;
}

// ---------------- LayerNorm (x + optional r addend = split-K reduction) ----------
__global__ void add_ln_kernel(const float* __restrict__ x,
                              const float* __restrict__ r,
                              const float* __restrict__ w,
                              const float* __restrict__ b,
                              float* __restrict__ out,
                              __nv_bfloat16* __restrict__ ohi,
                              __nv_bfloat16* __restrict__ olo) {
    int t = blockIdx.x;
    const float* xr = x + (size_t)t * Ee;
    const float* rr = r ? (r + (size_t)t * Ee) : nullptr;
    float vals[4];
    float s = 0.f, ss = 0.f;
    #pragma unroll
    for (int u = 0; u < 4; u++) {
        int e = threadIdx.x + u * 256;
        float v = xr[e];
        if (rr) v += rr[e];
        vals[u] = v;
        s += v; ss += v * v;
    }
    #pragma unroll
    for (int o = 16; o > 0; o >>= 1) {
        s  += __shfl_down_sync(0xffffffffu, s,  o);
        ss += __shfl_down_sync(0xffffffffu, ss, o);
    }
    __shared__ float sm[8], sm2[8], tot[2];
    int warp = threadIdx.x >> 5, lane = threadIdx.x & 31;
    if (lane == 0) { sm[warp] = s; sm2[warp] = ss; }
    __syncthreads();
    if (threadIdx.x == 0) {
        float S = 0.f, SS = 0.f;
        #pragma unroll
        for (int i = 0; i < 8; i++) { S += sm[i]; SS += sm2[i]; }
        tot[0] = S; tot[1] = SS;
    }
    __syncthreads();
    float mean = tot[0] * (1.0f / Ee);
    float var  = tot[1] * (1.0f / Ee) - mean * mean;
    float inv  = rsqrtf(var + 1e-5f);
    float* orow = out + (size_t)t * Ee;
    #pragma unroll
    for (int u = 0; u < 4; u++) {
        int e = threadIdx.x + u * 256;
        float v = (vals[u] - mean) * inv * w[e] + b[e];
        orow[e] = v;
        if (ohi) {
            __nv_bfloat16 h = __float2bfloat16(v);
            ohi[(size_t)t * Ee + e] = h;
            olo[(size_t)t * Ee + e] = __float2bfloat16(v - __bfloat162float(h));
        }
    }
}

// ---------------- mma.sync flash attention (bf16 hi/lo x3) -----------------------
#define FSROW 144
#define FPLANE (64 * FSROW)
#define FQ_OFF 0
#define FST_OFF (2 * FPLANE)
#define FDCOL_OFF (FST_OFF + 8 * FPLANE)
#define FPAD_OFF (FDCOL_OFF + 4096)
#define FLASH_SMEM (FPAD_OFF + 512)

__device__ __forceinline__ void flash_load_kv(uint32_t sb,
        const __nv_bfloat16* __restrict__ qkv_hi, const __nv_bfloat16* __restrict__ qkv_lo,
        int* __restrict__ padf, const int* __restrict__ seq,
        size_t tokbase, int j0, int buf, int h, int tid) {
    uint32_t base = sb + FST_OFF + buf * 4 * FPLANE;
    #pragma unroll
    for (int it = 0; it < 16; it++) {
        int idx = it * 128 + tid;
        int plane = idx >> 9;
        int rem = idx & 511;
        int row = rem >> 3, ch = rem & 7;
        const __nv_bfloat16* pb = (plane & 1) ? qkv_lo : qkv_hi;
        int eoff = (plane < 2) ? Ee : 2 * Ee;
        const __nv_bfloat16* src = pb + (tokbase + j0 + row) * (size_t)E3 + eoff + h * 64 + ch * 8;
        cpa16(base + plane * FPLANE + row * FSROW + ch * 16, src);
    }
    if (tid < 64) padf[buf * 64 + tid] = (seq[tokbase + j0 + tid] == 0);
}

__global__ __launch_bounds__(128)
void flash_mma_kernel(const __nv_bfloat16* __restrict__ qkv_hi,
                      const __nv_bfloat16* __restrict__ qkv_lo,
                      const float* __restrict__ dist_emb,
                      const int* __restrict__ seq,
                      __nv_bfloat16* __restrict__ ctx_hi,
                      __nv_bfloat16* __restrict__ ctx_lo) {
    extern __shared__ __align__(16) char fsm[];
    uint32_t sb = smem_u32(fsm);
    float* dcol = (float*)(fsm + FDCOL_OFF);
    int*   padf = (int*)(fsm + FPAD_OFF);

    int bh = blockIdx.y, bq = bh >> 4, h = bh & 15;
    int qt = gridDim.x - 1 - blockIdx.x;
    int i0q = qt * 64;
    int nt = qt + 1;
    int tid = threadIdx.x, wid = tid >> 5, lane = tid & 31;
    size_t tokbase = (size_t)bq * Ss;

    for (int e = tid; e < Ss; e += 128) dcol[e] = dist_emb[e * Hh + h];

    #pragma unroll
    for (int it = 0; it < 8; it++) {
        int idx = it * 128 + tid;
        int plane = idx >> 9;
        int rem = idx & 511;
        int row = rem >> 3, ch = rem & 7;
        const __nv_bfloat16* src = (plane ? qkv_lo : qkv_hi)
            + (tokbase + i0q + row) * (size_t)E3 + h * 64 + ch * 8;
        cpa16(sb + FQ_OFF + plane * FPLANE + row * FSROW + ch * 16, src);
    }
    flash_load_kv(sb, qkv_hi, qkv_lo, padf, seq, tokbase, 0, 0, h, tid);
    cpa_commit();
    if (nt > 1) { flash_load_kv(sb, qkv_hi, qkv_lo, padf, seq, tokbase, 64, 1, h, tid); cpa_commit(); }

    uint32_t qh[4][4], ql[4][4];
    float o[8][4];
    #pragma unroll
    for (int j = 0; j < 8; j++)
        #pragma unroll
        for (int r = 0; r < 4; r++) o[j][r] = 0.f;
    float m0 = -1e30f, m1 = -1e30f, l0 = 0.f, l1 = 0.f;

    for (int t = 0; t < nt; t++) {
        if (t < nt - 1) asm volatile("cp.async.wait_group 1;" ::: "memory");
        else            asm volatile("cp.async.wait_group 0;" ::: "memory");
        __syncthreads();
        if (t == 0) {
            #pragma unroll
            for (int kk = 0; kk < 4; kk++) {
                uint32_t addr = sb + FQ_OFF + (wid * 16 + (lane & 15)) * FSROW
                                + kk * 32 + (lane >> 4) * 16;
                ldsm4(qh[kk], addr);
                ldsm4(ql[kk], addr + FPLANE);
            }
        }
        int buf = t & 1;
        uint32_t kbase = sb + FST_OFF + buf * 4 * FPLANE;

        float s[8][4];
        #pragma unroll
        for (int j = 0; j < 8; j++)
            #pragma unroll
            for (int r = 0; r < 4; r++) s[j][r] = 0.f;
        #pragma unroll
        for (int kk = 0; kk < 4; kk++) {
            #pragma unroll
            for (int g = 0; g < 4; g++) {
                uint32_t kh[4], kl[4];
                uint32_t addr = kbase + (g * 16 + (lane & 15)) * FSROW
                                + kk * 32 + (lane >> 4) * 16;
                ldsm4(kh, addr);
                ldsm4(kl, addr + FPLANE);
                mma16816b(s[2*g],   qh[kk], kh[0], kh[2]);
                mma16816b(s[2*g],   qh[kk], kl[0], kl[2]);
                mma16816b(s[2*g],   ql[kk], kh[0], kh[2]);
                mma16816b(s[2*g+1], qh[kk], kh[1], kh[3]);
                mma16816b(s[2*g+1], qh[kk], kl[1], kl[3]);
                mma16816b(s[2*g+1], ql[kk], kh[1], kh[3]);
            }
        }
        int j0 = t * 64;
        int dbase = (i0q - j0) + wid * 16 + (lane >> 2);
        #pragma unroll
        for (int j = 0; j < 8; j++) {
            #pragma unroll
            for (int r = 0; r < 4; r++) {
                int col = j * 8 + (lane & 3) * 2 + (r & 1);
                int d = dbase + ((r & 2) << 2) - col;
                bool ok = (d >= 0) && (padf[buf * 64 + col] == 0);
                s[j][r] = ok ? s[j][r] * 0.125f + dcol[d] : -1e30f;
            }
        }
        float rm0 = -1e30f, rm1 = -1e30f;
        #pragma unroll
        for (int j = 0; j < 8; j++) {
            rm0 = fmaxf(rm0, fmaxf(s[j][0], s[j][1]));
            rm1 = fmaxf(rm1, fmaxf(s[j][2], s[j][3]));
        }
        rm0 = fmaxf(rm0, __shfl_xor_sync(0xffffffffu, rm0, 1));
        rm0 = fmaxf(rm0, __shfl_xor_sync(0xffffffffu, rm0, 2));
        rm1 = fmaxf(rm1, __shfl_xor_sync(0xffffffffu, rm1, 1));
        rm1 = fmaxf(rm1, __shfl_xor_sync(0xffffffffu, rm1, 2));
        float mn0 = fmaxf(m0, rm0), mn1 = fmaxf(m1, rm1);
        float c0 = __expf(m0 - mn0), c1 = __expf(m1 - mn1);
        m0 = mn0; m1 = mn1;
        float ps0 = 0.f, ps1 = 0.f;
        #pragma unroll
        for (int j = 0; j < 8; j++) {
            s[j][0] = __expf(s[j][0] - mn0); ps0 += s[j][0];
            s[j][1] = __expf(s[j][1] - mn0); ps0 += s[j][1];
            s[j][2] = __expf(s[j][2] - mn1); ps1 += s[j][2];
            s[j][3] = __expf(s[j][3] - mn1); ps1 += s[j][3];
        }
        l0 = l0 * c0 + ps0;
        l1 = l1 * c1 + ps1;
        #pragma unroll
        for (int j = 0; j < 8; j++) {
            o[j][0] *= c0; o[j][1] *= c0; o[j][2] *= c1; o[j][3] *= c1;
        }
        uint32_t ph[4][4], pl[4][4];
        #pragma unroll
        for (int u = 0; u < 4; u++) {
            packsplit2(s[2*u][0],   s[2*u][1],   ph[u][0], pl[u][0]);
            packsplit2(s[2*u][2],   s[2*u][3],   ph[u][1], pl[u][1]);
            packsplit2(s[2*u+1][0], s[2*u+1][1], ph[u][2], pl[u][2]);
            packsplit2(s[2*u+1][2], s[2*u+1][3], ph[u][3], pl[u][3]);
        }
        uint32_t vbase = kbase + 2 * FPLANE;
        #pragma unroll
        for (int u = 0; u < 4; u++) {
            #pragma unroll
            for (int g = 0; g < 4; g++) {
                uint32_t vh[4], vl[4];
                uint32_t addr = vbase + (u * 16 + (lane & 7) + ((lane >> 3) & 1) * 8) * FSROW
                                + g * 32 + (lane >> 4) * 16;
                ldsm4t(vh, addr);
                ldsm4t(vl, addr + FPLANE);
                mma16816b(o[2*g],   ph[u], vh[0], vh[1]);
                mma16816b(o[2*g],   ph[u], vl[0], vl[1]);
                mma16816b(o[2*g],   pl[u], vh[0], vh[1]);
                mma16816b(o[2*g+1], ph[u], vh[2], vh[3]);
                mma16816b(o[2*g+1], ph[u], vl[2], vl[3]);
                mma16816b(o[2*g+1], pl[u], vh[2], vh[3]);
            }
        }
        __syncthreads();
        if (t + 2 < nt) {
            flash_load_kv(sb, qkv_hi, qkv_lo, padf, seq, tokbase, (t + 2) * 64, buf, h, tid);
            cpa_commit();
        }
    }

    l0 += __shfl_xor_sync(0xffffffffu, l0, 1);
    l0 += __shfl_xor_sync(0xffffffffu, l0, 2);
    l1 += __shfl_xor_sync(0xffffffffu, l1, 1);
    l1 += __shfl_xor_sync(0xffffffffu, l1, 2);
    float inv0 = 1.0f / l0, inv1 = 1.0f / l1;

    size_t tok0 = tokbase + i0q + wid * 16 + (lane >> 2);
    int colb = h * 64 + (lane & 3) * 2;
    #pragma unroll
    for (int j = 0; j < 8; j++) {
        float v0 = o[j][0] * inv0, v1 = o[j][1] * inv0;
        float v2 = o[j][2] * inv1, v3 = o[j][3] * inv1;
        uint32_t h01, l01, h23, l23;
        packsplit2(v0, v1, h01, l01);
        packsplit2(v2, v3, h23, l23);
        *reinterpret_cast<uint32_t*>(ctx_hi + tok0 * Ee + colb + j * 8)       = h01;
        *reinterpret_cast<uint32_t*>(ctx_lo + tok0 * Ee + colb + j * 8)       = l01;
        *reinterpret_cast<uint32_t*>(ctx_hi + (tok0 + 8) * Ee + colb + j * 8) = h23;
        *reinterpret_cast<uint32_t*>(ctx_lo + (tok0 + 8) * Ee + colb + j * 8) = l23;
    }
}

// ---------------- host orchestration -------------------------------------------
static inline void split_on(cudaStream_t st, const float* src,
                            __nv_bfloat16* hi, __nv_bfloat16* lo, int n) {
    int n4 = n >> 2;
    split4_kernel<<<(n4 + 255) / 256, 256, 0, st>>>(src, hi, lo, n4);
}

extern "C" void kernel_launch(void* const* d_in, const int* in_sizes, int n_in,
                              void* d_out, int out_size) {
    const int*   seq        = (const int*)  d_in[0];
    const int*   map1       = (const int*)  d_in[1];
    const int*   map2       = (const int*)  d_in[2];
    const float* emb        = (const float*)d_in[3];
    const float* pos_emb    = (const float*)d_in[4];
    const float* dist_emb   = (const float*)d_in[5];
    const float* in_proj_w  = (const float*)d_in[6];
    const float* in_proj_b  = (const float*)d_in[7];
    const float* out_proj_w = (const float*)d_in[8];
    const float* out_proj_b = (const float*)d_in[9];
    const float* lin1_w     = (const float*)d_in[10];
    const float* lin1_b     = (const float*)d_in[11];
    const float* lin2_w     = (const float*)d_in[12];
    const float* lin2_b     = (const float*)d_in[13];
    const float* ln1_w      = (const float*)d_in[14];
    const float* ln1_b      = (const float*)d_in[15];
    const float* ln2_w      = (const float*)d_in[16];
    const float* ln2_b      = (const float*)d_in[17];
    const float* fnorm_w    = (const float*)d_in[18];
    const float* fnorm_b    = (const float*)d_in[19];
    const float* gen_w      = (const float*)d_in[20];
    const float* gen_b      = (const float*)d_in[21];
    float* out = (float*)d_out;

    float *x, *tmpp, *finp, *gbp;
    cudaGetSymbolAddress((void**)&x,    g_x);
    cudaGetSymbolAddress((void**)&tmpp, g_tmp);
    cudaGetSymbolAddress((void**)&finp, g_fin);
    cudaGetSymbolAddress((void**)&gbp,  g_gb);
    __nv_bfloat16 *wq_hi, *wq_lo, *wo_hi, *wo_lo, *w1_hi, *w1_lo, *w2_hi, *w2_lo;
    __nv_bfloat16 *x_hi, *x_lo, *qkv_hi, *qkv_lo, *c_hi, *c_lo, *h_hi, *h_lo, *gw_hi, *gw_lo;
    cudaGetSymbolAddress((void**)&wq_hi, g_wq_hi); cudaGetSymbolAddress((void**)&wq_lo, g_wq_lo);
    cudaGetSymbolAddress((void**)&wo_hi, g_wo_hi); cudaGetSymbolAddress((void**)&wo_lo, g_wo_lo);
    cudaGetSymbolAddress((void**)&w1_hi, g_w1_hi); cudaGetSymbolAddress((void**)&w1_lo, g_w1_lo);
    cudaGetSymbolAddress((void**)&w2_hi, g_w2_hi); cudaGetSymbolAddress((void**)&w2_lo, g_w2_lo);
    cudaGetSymbolAddress((void**)&x_hi,  g_x_hi);  cudaGetSymbolAddress((void**)&x_lo,  g_x_lo);
    cudaGetSymbolAddress((void**)&qkv_hi, g_qkv_hi); cudaGetSymbolAddress((void**)&qkv_lo, g_qkv_lo);
    cudaGetSymbolAddress((void**)&c_hi,  g_c_hi);  cudaGetSymbolAddress((void**)&c_lo,  g_c_lo);
    cudaGetSymbolAddress((void**)&h_hi,  g_h_hi);  cudaGetSymbolAddress((void**)&h_lo,  g_h_lo);
    cudaGetSymbolAddress((void**)&gw_hi, g_gw_hi); cudaGetSymbolAddress((void**)&gw_lo, g_gw_lo);

    cudaFuncSetAttribute(gemm_mma_kernel, cudaFuncAttributeMaxDynamicSharedMemorySize, GEMM_SMEM);
    cudaFuncSetAttribute(flash_mma_kernel, cudaFuncAttributeMaxDynamicSharedMemorySize, FLASH_SMEM);

    // persistent side stream + events (created on first, uncaptured, call)
    static cudaStream_t s2 = nullptr;
    static cudaEvent_t evFork = nullptr, evLayer[Ll], evHead = nullptr;
    if (!s2) {
        cudaStreamCreateWithFlags(&s2, cudaStreamNonBlocking);
        cudaEventCreateWithFlags(&evFork, cudaEventDisableTiming);
        for (int l = 0; l < Ll; l++)
            cudaEventCreateWithFlags(&evLayer[l], cudaEventDisableTiming);
        cudaEventCreateWithFlags(&evHead, cudaEventDisableTiming);
    }

    // fork side stream from origin, then per-layer weight splits on s2
    cudaEventRecord(evFork, 0);
    cudaStreamWaitEvent(s2, evFork, 0);
    for (int l = 0; l < Ll; l++) {
        split_on(s2, in_proj_w  + (size_t)l * E3 * Ee, wq_hi + (size_t)l * E3 * Ee,
                 wq_lo + (size_t)l * E3 * Ee, E3 * Ee);
        split_on(s2, out_proj_w + (size_t)l * Ee * Ee, wo_hi + (size_t)l * Ee * Ee,
                 wo_lo + (size_t)l * Ee * Ee, Ee * Ee);
        split_on(s2, lin1_w     + (size_t)l * Ff * Ee, w1_hi + (size_t)l * Ff * Ee,
                 w1_lo + (size_t)l * Ff * Ee, Ff * Ee);
        split_on(s2, lin2_w     + (size_t)l * Ee * Ff, w2_hi + (size_t)l * Ee * Ff,
                 w2_lo + (size_t)l * Ee * Ff, Ee * Ff);
        cudaEventRecord(evLayer[l], s2);
    }
    head_split_kernel<<<(NVPAD * Ee / 4) / 256, 256, 0, s2>>>(gen_w, gw_hi, gw_lo);
    head_bias_kernel<<<2, 256, 0, s2>>>(gen_b, gbp);
    cudaEventRecord(evHead, s2);

    // embedding (runs concurrently with early splits)
    embed_kernel<<<(Tt * Ee / 2) / 256, 256>>>(seq, map1, map2, emb, pos_emb, x, x_hi, x_lo);

    const size_t TE = (size_t)Tt * Ee;
    for (int l = 0; l < Ll; l++) {
        cudaStreamWaitEvent(0, evLayer[l], 0);   // layer-l weights ready
        // qkv = x @ Wq^T + b -> hi/lo
        gemm_mma_kernel<<<dim3(E3 / 128, Tt / 128, 1), 256, GEMM_SMEM>>>(
            x_hi, x_lo, wq_hi + (size_t)l * E3 * Ee, wq_lo + (size_t)l * E3 * Ee,
            in_proj_b + (size_t)l * E3, nullptr, nullptr, qkv_hi, qkv_lo,
            Tt, Ee, Ee, 0, E3, E3);
        // attention -> ctx hi/lo
        flash_mma_kernel<<<dim3(Ss / 64, Bb * Hh), 128, FLASH_SMEM>>>(
            qkv_hi, qkv_lo, dist_emb, seq, c_hi, c_lo);
        // tmp[z] = partial(ctx @ Wo^T); z0 += b + x   (split-K=2)
        gemm_mma_kernel<<<dim3(Ee / 128, Tt / 128, 2), 256, GEMM_SMEM>>>(
            c_hi, c_lo, wo_hi + (size_t)l * Ee * Ee, wo_lo + (size_t)l * Ee * Ee,
            out_proj_b + (size_t)l * Ee, x, tmpp, nullptr, nullptr,
            Tt, Ee, Ee / 2, 0, Ee, Ee);
        // x = LN(tmp0 + tmp1)
        add_ln_kernel<<<Tt, 256>>>(tmpp, tmpp + TE, ln1_w + (size_t)l * Ee, ln1_b + (size_t)l * Ee,
                                   x, x_hi, x_lo);
        // h = gelu(x @ W1^T + b) -> hi/lo
        gemm_mma_kernel<<<dim3(Ff / 128, Tt / 128, 1), 256, GEMM_SMEM>>>(
            x_hi, x_lo, w1_hi + (size_t)l * Ff * Ee, w1_lo + (size_t)l * Ff * Ee,
            lin1_b + (size_t)l * Ff, nullptr, nullptr, h_hi, h_lo,
            Tt, Ee, Ee, 1, Ff, Ff);
        // tmp[z] = partial(h @ W2^T); z0 += b + x   (split-K=2)
        gemm_mma_kernel<<<dim3(Ee / 128, Tt / 128, 2), 256, GEMM_SMEM>>>(
            h_hi, h_lo, w2_hi + (size_t)l * Ee * Ff, w2_lo + (size_t)l * Ee * Ff,
            lin2_b + (size_t)l * Ee, x, tmpp, nullptr, nullptr,
            Tt, Ff, Ff / 2, 0, Ee, Ee);
        // x = LN(tmp0 + tmp1)
        add_ln_kernel<<<Tt, 256>>>(tmpp, tmpp + TE, ln2_w + (size_t)l * Ee, ln2_b + (size_t)l * Ee,
                                   x, x_hi, x_lo);
    }

    // final norm -> fp32 + hi/lo
    add_ln_kernel<<<Tt, 256>>>(x, nullptr, fnorm_w, fnorm_b, finp, x_hi, x_lo);
    // logits = xn @ gen_w^T + gen_b (padded N=512, guarded to 400)
    cudaStreamWaitEvent(0, evHead, 0);
    gemm_mma_kernel<<<dim3(NVPAD / 128, Tt / 128, 1), 256, GEMM_SMEM>>>(
        x_hi, x_lo, gw_hi, gw_lo, gbp, nullptr, out, nullptr, nullptr,
        Tt, Ee, Ee, 0, Vv, Vv);
}

// round 17
// speedup vs baseline: 1.1085x; 1.0037x over previous
#include <cuda_runtime.h>
#include <cuda_bf16.h>
#include <math.h>
#include <stdint.h>

// Problem constants
#define Bb 2
#define Ss 1024
#define Ee 1024
#define Hh 16
#define DHd 64
#define Ll 6
#define Ff 4096
#define Vv 400
#define Tt (Bb*Ss)        // 2048 tokens
#define E3 (3*Ee)         // 3072
#define NVPAD 512

// ---------------- scratch (device globals; no runtime allocation) -------------
__device__ float g_x  [Tt * Ee];
__device__ float g_tmp[2 * Tt * Ee];   // split-K partials (z=0 carries bias+residual)
__device__ float g_fin[Tt * Ee];

__device__ __nv_bfloat16 g_wq_hi[Ll * E3 * Ee], g_wq_lo[Ll * E3 * Ee];
__device__ __nv_bfloat16 g_wo_hi[Ll * Ee * Ee], g_wo_lo[Ll * Ee * Ee];
__device__ __nv_bfloat16 g_w1_hi[Ll * Ff * Ee], g_w1_lo[Ll * Ff * Ee];
__device__ __nv_bfloat16 g_w2_hi[Ll * Ee * Ff], g_w2_lo[Ll * Ee * Ff];
__device__ __nv_bfloat16 g_x_hi [Tt * Ee],  g_x_lo [Tt * Ee];
__device__ __nv_bfloat16 g_qkv_hi[Tt * E3], g_qkv_lo[Tt * E3];
__device__ __nv_bfloat16 g_c_hi [Tt * Ee],  g_c_lo [Tt * Ee];
__device__ __nv_bfloat16 g_h_hi [Tt * Ff],  g_h_lo [Tt * Ff];
__device__ __nv_bfloat16 g_gw_hi[NVPAD * Ee], g_gw_lo[NVPAD * Ee];
__device__ float g_gb[NVPAD];

// ---------------- PTX helpers (base sm_103 ONLY) --------------------------------
__device__ __forceinline__ uint32_t smem_u32(const void* p) {
    uint32_t a;
    asm("{ .reg .u64 t; cvta.to.shared.u64 t, %1; cvt.u32.u64 %0, t; }" : "=r"(a) : "l"(p));
    return a;
}
__device__ __forceinline__ void cpa16(uint32_t dst, const void* src) {
    asm volatile("cp.async.cg.shared.global [%0], [%1], 16;" :: "r"(dst), "l"(src) : "memory");
}
__device__ __forceinline__ void cpa_commit() {
    asm volatile("cp.async.commit_group;" ::: "memory");
}
__device__ __forceinline__ void ldsm4(uint32_t* r, uint32_t addr) {
    asm volatile("ldmatrix.sync.aligned.m8n8.x4.shared.b16 {%0,%1,%2,%3}, [%4];"
                 : "=r"(r[0]), "=r"(r[1]), "=r"(r[2]), "=r"(r[3]) : "r"(addr));
}
__device__ __forceinline__ void ldsm4t(uint32_t* r, uint32_t addr) {
    asm volatile("ldmatrix.sync.aligned.m8n8.x4.trans.shared.b16 {%0,%1,%2,%3}, [%4];"
                 : "=r"(r[0]), "=r"(r[1]), "=r"(r[2]), "=r"(r[3]) : "r"(addr));
}
__device__ __forceinline__ void mma16816(float* c, const uint32_t* a, const uint32_t* b) {
    asm volatile(
        "mma.sync.aligned.m16n8k16.row.col.f32.bf16.bf16.f32 "
        "{%0,%1,%2,%3}, {%4,%5,%6,%7}, {%8,%9}, {%0,%1,%2,%3};"
        : "+f"(c[0]), "+f"(c[1]), "+f"(c[2]), "+f"(c[3])
        : "r"(a[0]), "r"(a[1]), "r"(a[2]), "r"(a[3]), "r"(b[0]), "r"(b[1]));
}
__device__ __forceinline__ void mma16816b(float* c, const uint32_t* a, uint32_t b0, uint32_t b1) {
    asm volatile(
        "mma.sync.aligned.m16n8k16.row.col.f32.bf16.bf16.f32 "
        "{%0,%1,%2,%3}, {%4,%5,%6,%7}, {%8,%9}, {%0,%1,%2,%3};"
        : "+f"(c[0]), "+f"(c[1]), "+f"(c[2]), "+f"(c[3])
        : "r"(a[0]), "r"(a[1]), "r"(a[2]), "r"(a[3]), "r"(b0), "r"(b1));
}
__device__ __forceinline__ float gelu_exact(float v) {
    return 0.5f * v * (1.0f + erff(v * 0.70710678118654752f));
}
__device__ __forceinline__ void packsplit2(float a, float b, uint32_t& hi, uint32_t& lo) {
    __nv_bfloat16 ah = __float2bfloat16(a), bh = __float2bfloat16(b);
    __nv_bfloat16 al = __float2bfloat16(a - __bfloat162float(ah));
    __nv_bfloat16 bl = __float2bfloat16(b - __bfloat162float(bh));
    hi = (uint32_t)__bfloat16_as_ushort(ah) | ((uint32_t)__bfloat16_as_ushort(bh) << 16);
    lo = (uint32_t)__bfloat16_as_ushort(al) | ((uint32_t)__bfloat16_as_ushort(bl) << 16);
}

// ---------------- fp32 -> bf16 hi/lo split (weights) ----------------------------
__global__ void split4_kernel(const float* __restrict__ x,
                              __nv_bfloat16* __restrict__ hi,
                              __nv_bfloat16* __restrict__ lo, int n4) {
    int i = blockIdx.x * blockDim.x + threadIdx.x;
    if (i >= n4) return;
    float4 v = ((const float4*)x)[i];
    uint32_t h0, l0, h1, l1;
    packsplit2(v.x, v.y, h0, l0);
    packsplit2(v.z, v.w, h1, l1);
    ((uint2*)hi)[i] = make_uint2(h0, h1);
    ((uint2*)lo)[i] = make_uint2(l0, l1);
}
__global__ void head_split_kernel(const float* __restrict__ gw,
                                  __nv_bfloat16* __restrict__ hi,
                                  __nv_bfloat16* __restrict__ lo) {
    int i = blockIdx.x * blockDim.x + threadIdx.x;
    int row = (i * 4) >> 10;
    float4 v = make_float4(0.f, 0.f, 0.f, 0.f);
    if (row < Vv) v = ((const float4*)gw)[i];
    uint32_t h0, l0, h1, l1;
    packsplit2(v.x, v.y, h0, l0);
    packsplit2(v.z, v.w, h1, l1);
    ((uint2*)hi)[i] = make_uint2(h0, h1);
    ((uint2*)lo)[i] = make_uint2(l0, l1);
}
__global__ void head_bias_kernel(const float* __restrict__ gb, float* __restrict__ out) {
    int i = blockIdx.x * blockDim.x + threadIdx.x;
    if (i < NVPAD) out[i] = (i < Vv) ? gb[i] : 0.f;
}

// ---------------- tensor-core GEMM via mma.sync (bf16x3, 128x128x32, split-K) ----
#define SROWB 80
#define PLANEB (128 * SROWB)
#define STAGEB (4 * PLANEB)        // 40960 B
#define GEMM_SMEM (2 * STAGEB)     // 81920 -> 2 CTAs/SM

__device__ __forceinline__ void load_stage(uint32_t dst,
        const __nv_bfloat16* __restrict__ Ahi, const __nv_bfloat16* __restrict__ Alo,
        const __nv_bfloat16* __restrict__ Bhi, const __nv_bfloat16* __restrict__ Blo,
        int bm, int bn, int ldK, int koff, int kt, int tid) {
    const __nv_bfloat16* srcs[4] = {Ahi, Alo, Bhi, Blo};
    #pragma unroll
    for (int c = 0; c < 8; c++) {
        int plane = c >> 1;
        int rem = (c & 1) * 256 + tid;
        int row = rem >> 2;
        int cc  = rem & 3;
        int base_row = (plane < 2 ? bm : bn) + row;
        const __nv_bfloat16* src = srcs[plane] + (size_t)base_row * ldK + koff + kt * 32 + cc * 8;
        cpa16(dst + plane * PLANEB + row * SROWB + cc * 16, src);
    }
    cpa_commit();
}

__global__ __launch_bounds__(256, 2)
void gemm_mma_kernel(const __nv_bfloat16* __restrict__ Ahi,
                     const __nv_bfloat16* __restrict__ Alo,
                     const __nv_bfloat16* __restrict__ Bhi,
                     const __nv_bfloat16* __restrict__ Blo,
                     const float* __restrict__ bias,
                     const float* __restrict__ addf,
                     float* __restrict__ Cf,
                     __nv_bfloat16* __restrict__ Chi,
                     __nv_bfloat16* __restrict__ Clo,
                     int M, int ldK, int Ksub, int act, int ldC, int Nv) {
    extern __shared__ __align__(16) char smem[];
    uint32_t sb = smem_u32(smem);
    int tid = threadIdx.x, wid = tid >> 5, lane = tid & 31;
    int bm = blockIdx.y << 7, bn = blockIdx.x << 7;
    int z = blockIdx.z;
    int koff = z * Ksub;
    int warp_m = (wid >> 2) * 64;
    int warp_n = (wid & 3) * 32;

    float acc[4][4][4];
    #pragma unroll
    for (int i = 0; i < 4; i++)
        #pragma unroll
        for (int j = 0; j < 4; j++)
            #pragma unroll
            for (int k = 0; k < 4; k++) acc[i][j][k] = 0.f;

    const int KT = Ksub >> 5;
    load_stage(sb,          Ahi, Alo, Bhi, Blo, bm, bn, ldK, koff, 0, tid);
    load_stage(sb + STAGEB, Ahi, Alo, Bhi, Blo, bm, bn, ldK, koff, 1, tid);

    int a_row = warp_m + (lane & 15);
    int a_koff = (lane >> 4) << 4;
    int b_row = warp_n + (lane & 7) + ((lane >> 4) << 3);
    int b_koff = ((lane >> 3) & 1) << 4;

    for (int kt = 0; kt < KT; kt++) {
        if (kt + 1 < KT) asm volatile("cp.async.wait_group 1;" ::: "memory");
        else             asm volatile("cp.async.wait_group 0;" ::: "memory");
        __syncthreads();

        uint32_t stage = sb + (kt & 1) * STAGEB;
        #pragma unroll
        for (int ks = 0; ks < 2; ks++) {
            int kb = ks * 32;
            uint32_t ah[4][4], al[4][4], bh[2][4], bl[2][4];
            uint32_t a_addr = stage + a_row * SROWB + kb + a_koff;
            #pragma unroll
            for (int mt = 0; mt < 4; mt++) {
                ldsm4(ah[mt], a_addr + mt * 16 * SROWB);
                ldsm4(al[mt], a_addr + PLANEB + mt * 16 * SROWB);
            }
            uint32_t b_addr = stage + 2 * PLANEB + b_row * SROWB + kb + b_koff;
            #pragma unroll
            for (int p = 0; p < 2; p++) {
                ldsm4(bh[p], b_addr + p * 16 * SROWB);
                ldsm4(bl[p], b_addr + PLANEB + p * 16 * SROWB);
            }
            #pragma unroll
            for (int mt = 0; mt < 4; mt++) {
                #pragma unroll
                for (int j = 0; j < 4; j++) {
                    int p = j >> 1, o = (j & 1) * 2;
                    mma16816(acc[mt][j], ah[mt], &bh[p][o]);
                    mma16816(acc[mt][j], ah[mt], &bl[p][o]);
                    mma16816(acc[mt][j], al[mt], &bh[p][o]);
                }
            }
        }
        __syncthreads();
        if (kt + 2 < KT)
            load_stage(sb + (kt & 1) * STAGEB, Ahi, Alo, Bhi, Blo, bm, bn, ldK, koff, kt + 2, tid);
    }

    float* Cfz = Cf ? Cf + (size_t)z * M * ldC : nullptr;
    int r0 = bm + warp_m + (lane >> 2);
    int c0 = bn + warp_n + (lane & 3) * 2;
    #pragma unroll
    for (int j = 0; j < 4; j++) {
        int col = c0 + j * 8;
        if (col >= Nv) continue;
        float b0 = 0.f, b1 = 0.f;
        if (z == 0) { b0 = __ldg(bias + col); b1 = __ldg(bias + col + 1); }
        #pragma unroll
        for (int mt = 0; mt < 4; mt++) {
            int row = r0 + mt * 16;
            float v0 = acc[mt][j][0] + b0, v1 = acc[mt][j][1] + b1;
            float v2 = acc[mt][j][2] + b0, v3 = acc[mt][j][3] + b1;
            if (act) { v0 = gelu_exact(v0); v1 = gelu_exact(v1);
                       v2 = gelu_exact(v2); v3 = gelu_exact(v3); }
            if (addf && z == 0) {
                float2 a0 = *(const float2*)(addf + (size_t)row * ldC + col);
                float2 a1 = *(const float2*)(addf + (size_t)(row + 8) * ldC + col);
                v0 += a0.x; v1 += a0.y; v2 += a1.x; v3 += a1.y;
            }
            if (Cfz) {
                *(float2*)(Cfz + (size_t)row * ldC + col)       = make_float2(v0, v1);
                *(float2*)(Cfz + (size_t)(row + 8) * ldC + col) = make_float2(v2, v3);
            }
            if (Chi) {
                uint32_t h01, l01, h23, l23;
                packsplit2(v0, v1, h01, l01);
                packsplit2(v2, v3, h23, l23);
                *reinterpret_cast<uint32_t*>(Chi + (size_t)row * ldC + col)       = h01;
                *reinterpret_cast<uint32_t*>(Clo + (size_t)row * ldC + col)       = l01;
                *reinterpret_cast<uint32_t*>(Chi + (size_t)(row + 8) * ldC + col) = h23;
                *reinterpret_cast<uint32_t*>(Clo + (size_t)(row + 8) * ldC + col) = l23;
            }
        }
    }
}

// ---------------- embedding (fp32 + hi/lo) --------------------------------------
__global__ void embed_kernel(const int* __restrict__ seq,
                             const int* __restrict__ map1,
                             const int* __restrict__ map2,
                             const float* __restrict__ emb,
                             const float* __restrict__ pos,
                             float* __restrict__ x,
                             __nv_bfloat16* __restrict__ xhi,
                             __nv_bfloat16* __restrict__ xlo) {
    int idx2 = blockIdx.x * blockDim.x + threadIdx.x;
    int idx = idx2 * 2;
    int t = idx >> 10;
    int e = idx & 1023;
    int s = t & 1023;
    int tok = seq[t];
    int m1 = map1[tok], m2 = map2[tok];
    float v0 = (emb[(size_t)m1 * Ee + e] + emb[(size_t)m2 * Ee + e]) * 16.0f
               + pos[(size_t)s * Ee + e];
    float v1 = (emb[(size_t)m1 * Ee + e + 1] + emb[(size_t)m2 * Ee + e + 1]) * 16.0f
               + pos[(size_t)s * Ee + e + 1];
    *(float2*)(x + idx) = make_float2(v0, v1);
    uint32_t h, l;
    packsplit2(v0, v1, h, l);
    *reinterpret_cast<uint32_t*>(xhi + idx) = h;
    *reinterpret_cast<uint32_t*>(xlo + idx) = l;
}

// ---------------- LayerNorm (x + optional r addend = split-K reduction) ----------
__global__ void add_ln_kernel(const float* __restrict__ x,
                              const float* __restrict__ r,
                              const float* __restrict__ w,
                              const float* __restrict__ b,
                              float* __restrict__ out,
                              __nv_bfloat16* __restrict__ ohi,
                              __nv_bfloat16* __restrict__ olo) {
    int t = blockIdx.x;
    const float* xr = x + (size_t)t * Ee;
    const float* rr = r ? (r + (size_t)t * Ee) : nullptr;
    float vals[4];
    float s = 0.f, ss = 0.f;
    #pragma unroll
    for (int u = 0; u < 4; u++) {
        int e = threadIdx.x + u * 256;
        float v = xr[e];
        if (rr) v += rr[e];
        vals[u] = v;
        s += v; ss += v * v;
    }
    #pragma unroll
    for (int o = 16; o > 0; o >>= 1) {
        s  += __shfl_down_sync(0xffffffffu, s,  o);
        ss += __shfl_down_sync(0xffffffffu, ss, o);
    }
    __shared__ float sm[8], sm2[8], tot[2];
    int warp = threadIdx.x >> 5, lane = threadIdx.x & 31;
    if (lane == 0) { sm[warp] = s; sm2[warp] = ss; }
    __syncthreads();
    if (threadIdx.x == 0) {
        float S = 0.f, SS = 0.f;
        #pragma unroll
        for (int i = 0; i < 8; i++) { S += sm[i]; SS += sm2[i]; }
        tot[0] = S; tot[1] = SS;
    }
    __syncthreads();
    float mean = tot[0] * (1.0f / Ee);
    float var  = tot[1] * (1.0f / Ee) - mean * mean;
    float inv  = rsqrtf(var + 1e-5f);
    float* orow = out + (size_t)t * Ee;
    #pragma unroll
    for (int u = 0; u < 4; u++) {
        int e = threadIdx.x + u * 256;
        float v = (vals[u] - mean) * inv * w[e] + b[e];
        orow[e] = v;
        if (ohi) {
            __nv_bfloat16 h = __float2bfloat16(v);
            ohi[(size_t)t * Ee + e] = h;
            olo[(size_t)t * Ee + e] = __float2bfloat16(v - __bfloat162float(h));
        }
    }
}

// ---------------- mma.sync flash attention (bf16 hi/lo x3, 128-query CTAs) -------
// grid (S/128 [reversed], B*H), 256 threads (8 warps), warp = 16 query rows.
#define FSROW 144
#define FPLANE (64 * FSROW)           // 9216 (K/V plane, 64 rows)
#define FQPLANE (128 * FSROW)         // 18432 (Q plane, 128 rows)
#define FQ_OFF 0                      // 2 Q planes = 36864
#define FST_OFF (2 * FQPLANE)         // 36864; 2 bufs x 4 planes = 73728 -> 110592
#define FDCOL_OFF (FST_OFF + 8 * FPLANE)      // 110592, bf16[1024] = 2048
#define FPAD_OFF (FDCOL_OFF + 2048)           // 112640
#define FLASH_SMEM (FPAD_OFF + 512)           // 113152 -> 2 CTAs/SM

__device__ __forceinline__ void flash_load_kv(uint32_t sb,
        const __nv_bfloat16* __restrict__ qkv_hi, const __nv_bfloat16* __restrict__ qkv_lo,
        int* __restrict__ padf, const int* __restrict__ seq,
        size_t tokbase, int j0, int buf, int h, int tid) {
    uint32_t base = sb + FST_OFF + buf * 4 * FPLANE;
    #pragma unroll
    for (int it = 0; it < 8; it++) {
        int idx = it * 256 + tid;      // 0..2047
        int plane = idx >> 9;          // 0:Khi 1:Klo 2:Vhi 3:Vlo
        int rem = idx & 511;
        int row = rem >> 3, ch = rem & 7;
        const __nv_bfloat16* pb = (plane & 1) ? qkv_lo : qkv_hi;
        int eoff = (plane < 2) ? Ee : 2 * Ee;
        const __nv_bfloat16* src = pb + (tokbase + j0 + row) * (size_t)E3 + eoff + h * 64 + ch * 8;
        cpa16(base + plane * FPLANE + row * FSROW + ch * 16, src);
    }
    if (tid < 64) padf[buf * 64 + tid] = (seq[tokbase + j0 + tid] == 0);
}

__global__ __launch_bounds__(256)
void flash_mma_kernel(const __nv_bfloat16* __restrict__ qkv_hi,
                      const __nv_bfloat16* __restrict__ qkv_lo,
                      const float* __restrict__ dist_emb,
                      const int* __restrict__ seq,
                      __nv_bfloat16* __restrict__ ctx_hi,
                      __nv_bfloat16* __restrict__ ctx_lo) {
    extern __shared__ __align__(16) char fsm[];
    uint32_t sb = smem_u32(fsm);
    __nv_bfloat16* dcol = (__nv_bfloat16*)(fsm + FDCOL_OFF);
    int* padf = (int*)(fsm + FPAD_OFF);

    int bh = blockIdx.y, bq = bh >> 4, h = bh & 15;
    int qt = gridDim.x - 1 - blockIdx.x;     // long CTAs launch first
    int i0q = qt * 128;
    int nt = 2 * qt + 2;
    int tid = threadIdx.x, wid = tid >> 5, lane = tid & 31;
    size_t tokbase = (size_t)bq * Ss;

    for (int e = tid; e < Ss; e += 256)
        dcol[e] = __float2bfloat16(dist_emb[e * Hh + h]);

    // Q planes (hi, lo): 128 rows each
    #pragma unroll
    for (int it = 0; it < 8; it++) {
        int idx = it * 256 + tid;      // 0..2047
        int plane = idx >> 10;
        int rem = idx & 1023;
        int row = rem >> 3, ch = rem & 7;
        const __nv_bfloat16* src = (plane ? qkv_lo : qkv_hi)
            + (tokbase + i0q + row) * (size_t)E3 + h * 64 + ch * 8;
        cpa16(sb + FQ_OFF + plane * FQPLANE + row * FSROW + ch * 16, src);
    }
    flash_load_kv(sb, qkv_hi, qkv_lo, padf, seq, tokbase, 0, 0, h, tid);
    cpa_commit();
    flash_load_kv(sb, qkv_hi, qkv_lo, padf, seq, tokbase, 64, 1, h, tid);
    cpa_commit();

    uint32_t qh[4][4], ql[4][4];
    float o[8][4];
    #pragma unroll
    for (int j = 0; j < 8; j++)
        #pragma unroll
        for (int r = 0; r < 4; r++) o[j][r] = 0.f;
    float m0 = -1e30f, m1 = -1e30f, l0 = 0.f, l1 = 0.f;

    for (int t = 0; t < nt; t++) {
        if (t < nt - 1) asm volatile("cp.async.wait_group 1;" ::: "memory");
        else            asm volatile("cp.async.wait_group 0;" ::: "memory");
        __syncthreads();
        if (t == 0) {
            #pragma unroll
            for (int kk = 0; kk < 4; kk++) {
                uint32_t addr = sb + FQ_OFF + (wid * 16 + (lane & 15)) * FSROW
                                + kk * 32 + (lane >> 4) * 16;
                ldsm4(qh[kk], addr);
                ldsm4(ql[kk], addr + FQPLANE);
            }
        }
        int buf = t & 1;
        uint32_t kbase = sb + FST_OFF + buf * 4 * FPLANE;

        // ---- S = Q K^T (hi/lo x3) ----
        float s[8][4];
        #pragma unroll
        for (int j = 0; j < 8; j++)
            #pragma unroll
            for (int r = 0; r < 4; r++) s[j][r] = 0.f;
        #pragma unroll
        for (int kk = 0; kk < 4; kk++) {
            #pragma unroll
            for (int g = 0; g < 4; g++) {
                uint32_t kh[4], kl[4];
                uint32_t addr = kbase + (g * 16 + (lane & 15)) * FSROW
                                + kk * 32 + (lane >> 4) * 16;
                ldsm4(kh, addr);
                ldsm4(kl, addr + FPLANE);
                mma16816b(s[2*g],   qh[kk], kh[0], kh[2]);
                mma16816b(s[2*g],   qh[kk], kl[0], kl[2]);
                mma16816b(s[2*g],   ql[kk], kh[0], kh[2]);
                mma16816b(s[2*g+1], qh[kk], kh[1], kh[3]);
                mma16816b(s[2*g+1], qh[kk], kl[1], kl[3]);
                mma16816b(s[2*g+1], ql[kk], kh[1], kh[3]);
            }
        }
        // ---- bias + causal + pad mask ----
        int j0 = t * 64;
        int dbase = (i0q - j0) + wid * 16 + (lane >> 2);
        #pragma unroll
        for (int j = 0; j < 8; j++) {
            #pragma unroll
            for (int r = 0; r < 4; r++) {
                int col = j * 8 + (lane & 3) * 2 + (r & 1);
                int d = dbase + ((r & 2) << 2) - col;
                bool ok = (d >= 0) && (padf[buf * 64 + col] == 0);
                s[j][r] = ok ? s[j][r] * 0.125f + __bfloat162float(dcol[d]) : -1e30f;
            }
        }
        // ---- online softmax ----
        float rm0 = -1e30f, rm1 = -1e30f;
        #pragma unroll
        for (int j = 0; j < 8; j++) {
            rm0 = fmaxf(rm0, fmaxf(s[j][0], s[j][1]));
            rm1 = fmaxf(rm1, fmaxf(s[j][2], s[j][3]));
        }
        rm0 = fmaxf(rm0, __shfl_xor_sync(0xffffffffu, rm0, 1));
        rm0 = fmaxf(rm0, __shfl_xor_sync(0xffffffffu, rm0, 2));
        rm1 = fmaxf(rm1, __shfl_xor_sync(0xffffffffu, rm1, 1));
        rm1 = fmaxf(rm1, __shfl_xor_sync(0xffffffffu, rm1, 2));
        float mn0 = fmaxf(m0, rm0), mn1 = fmaxf(m1, rm1);
        float c0 = __expf(m0 - mn0), c1 = __expf(m1 - mn1);
        m0 = mn0; m1 = mn1;
        float ps0 = 0.f, ps1 = 0.f;
        #pragma unroll
        for (int j = 0; j < 8; j++) {
            s[j][0] = __expf(s[j][0] - mn0); ps0 += s[j][0];
            s[j][1] = __expf(s[j][1] - mn0); ps0 += s[j][1];
            s[j][2] = __expf(s[j][2] - mn1); ps1 += s[j][2];
            s[j][3] = __expf(s[j][3] - mn1); ps1 += s[j][3];
        }
        l0 = l0 * c0 + ps0;
        l1 = l1 * c1 + ps1;
        #pragma unroll
        for (int j = 0; j < 8; j++) {
            o[j][0] *= c0; o[j][1] *= c0; o[j][2] *= c1; o[j][3] *= c1;
        }
        // ---- P fragments (hi/lo) ----
        uint32_t ph[4][4], pl[4][4];
        #pragma unroll
        for (int u = 0; u < 4; u++) {
            packsplit2(s[2*u][0],   s[2*u][1],   ph[u][0], pl[u][0]);
            packsplit2(s[2*u][2],   s[2*u][3],   ph[u][1], pl[u][1]);
            packsplit2(s[2*u+1][0], s[2*u+1][1], ph[u][2], pl[u][2]);
            packsplit2(s[2*u+1][2], s[2*u+1][3], ph[u][3], pl[u][3]);
        }
        // ---- O += P V (hi/lo x3) ----
        uint32_t vbase = kbase + 2 * FPLANE;
        #pragma unroll
        for (int u = 0; u < 4; u++) {
            #pragma unroll
            for (int g = 0; g < 4; g++) {
                uint32_t vh[4], vl[4];
                uint32_t addr = vbase + (u * 16 + (lane & 7) + ((lane >> 3) & 1) * 8) * FSROW
                                + g * 32 + (lane >> 4) * 16;
                ldsm4t(vh, addr);
                ldsm4t(vl, addr + FPLANE);
                mma16816b(o[2*g],   ph[u], vh[0], vh[1]);
                mma16816b(o[2*g],   ph[u], vl[0], vl[1]);
                mma16816b(o[2*g],   pl[u], vh[0], vh[1]);
                mma16816b(o[2*g+1], ph[u], vh[2], vh[3]);
                mma16816b(o[2*g+1], ph[u], vl[2], vl[3]);
                mma16816b(o[2*g+1], pl[u], vh[2], vh[3]);
            }
        }
        __syncthreads();
        if (t + 2 < nt) {
            flash_load_kv(sb, qkv_hi, qkv_lo, padf, seq, tokbase, (t + 2) * 64, buf, h, tid);
            cpa_commit();
        }
    }

    // ---- finalize ----
    l0 += __shfl_xor_sync(0xffffffffu, l0, 1);
    l0 += __shfl_xor_sync(0xffffffffu, l0, 2);
    l1 += __shfl_xor_sync(0xffffffffu, l1, 1);
    l1 += __shfl_xor_sync(0xffffffffu, l1, 2);
    float inv0 = 1.0f / l0, inv1 = 1.0f / l1;

    size_t tok0 = tokbase + i0q + wid * 16 + (lane >> 2);
    int colb = h * 64 + (lane & 3) * 2;
    #pragma unroll
    for (int j = 0; j < 8; j++) {
        float v0 = o[j][0] * inv0, v1 = o[j][1] * inv0;
        float v2 = o[j][2] * inv1, v3 = o[j][3] * inv1;
        uint32_t h01, l01, h23, l23;
        packsplit2(v0, v1, h01, l01);
        packsplit2(v2, v3, h23, l23);
        *reinterpret_cast<uint32_t*>(ctx_hi + tok0 * Ee + colb + j * 8)       = h01;
        *reinterpret_cast<uint32_t*>(ctx_lo + tok0 * Ee + colb + j * 8)       = l01;
        *reinterpret_cast<uint32_t*>(ctx_hi + (tok0 + 8) * Ee + colb + j * 8) = h23;
        *reinterpret_cast<uint32_t*>(ctx_lo + (tok0 + 8) * Ee + colb + j * 8) = l23;
    }
}

// ---------------- host orchestration -------------------------------------------
static inline void split_on(cudaStream_t st, const float* src,
                            __nv_bfloat16* hi, __nv_bfloat16* lo, int n) {
    int n4 = n >> 2;
    split4_kernel<<<(n4 + 255) / 256, 256, 0, st>>>(src, hi, lo, n4);
}

extern "C" void kernel_launch(void* const* d_in, const int* in_sizes, int n_in,
                              void* d_out, int out_size) {
    const int*   seq        = (const int*)  d_in[0];
    const int*   map1       = (const int*)  d_in[1];
    const int*   map2       = (const int*)  d_in[2];
    const float* emb        = (const float*)d_in[3];
    const float* pos_emb    = (const float*)d_in[4];
    const float* dist_emb   = (const float*)d_in[5];
    const float* in_proj_w  = (const float*)d_in[6];
    const float* in_proj_b  = (const float*)d_in[7];
    const float* out_proj_w = (const float*)d_in[8];
    const float* out_proj_b = (const float*)d_in[9];
    const float* lin1_w     = (const float*)d_in[10];
    const float* lin1_b     = (const float*)d_in[11];
    const float* lin2_w     = (const float*)d_in[12];
    const float* lin2_b     = (const float*)d_in[13];
    const float* ln1_w      = (const float*)d_in[14];
    const float* ln1_b      = (const float*)d_in[15];
    const float* ln2_w      = (const float*)d_in[16];
    const float* ln2_b      = (const float*)d_in[17];
    const float* fnorm_w    = (const float*)d_in[18];
    const float* fnorm_b    = (const float*)d_in[19];
    const float* gen_w      = (const float*)d_in[20];
    const float* gen_b      = (const float*)d_in[21];
    float* out = (float*)d_out;

    float *x, *tmpp, *finp, *gbp;
    cudaGetSymbolAddress((void**)&x,    g_x);
    cudaGetSymbolAddress((void**)&tmpp, g_tmp);
    cudaGetSymbolAddress((void**)&finp, g_fin);
    cudaGetSymbolAddress((void**)&gbp,  g_gb);
    __nv_bfloat16 *wq_hi, *wq_lo, *wo_hi, *wo_lo, *w1_hi, *w1_lo, *w2_hi, *w2_lo;
    __nv_bfloat16 *x_hi, *x_lo, *qkv_hi, *qkv_lo, *c_hi, *c_lo, *h_hi, *h_lo, *gw_hi, *gw_lo;
    cudaGetSymbolAddress((void**)&wq_hi, g_wq_hi); cudaGetSymbolAddress((void**)&wq_lo, g_wq_lo);
    cudaGetSymbolAddress((void**)&wo_hi, g_wo_hi); cudaGetSymbolAddress((void**)&wo_lo, g_wo_lo);
    cudaGetSymbolAddress((void**)&w1_hi, g_w1_hi); cudaGetSymbolAddress((void**)&w1_lo, g_w1_lo);
    cudaGetSymbolAddress((void**)&w2_hi, g_w2_hi); cudaGetSymbolAddress((void**)&w2_lo, g_w2_lo);
    cudaGetSymbolAddress((void**)&x_hi,  g_x_hi);  cudaGetSymbolAddress((void**)&x_lo,  g_x_lo);
    cudaGetSymbolAddress((void**)&qkv_hi, g_qkv_hi); cudaGetSymbolAddress((void**)&qkv_lo, g_qkv_lo);
    cudaGetSymbolAddress((void**)&c_hi,  g_c_hi);  cudaGetSymbolAddress((void**)&c_lo,  g_c_lo);
    cudaGetSymbolAddress((void**)&h_hi,  g_h_hi);  cudaGetSymbolAddress((void**)&h_lo,  g_h_lo);
    cudaGetSymbolAddress((void**)&gw_hi, g_gw_hi); cudaGetSymbolAddress((void**)&gw_lo, g_gw_lo);

    cudaFuncSetAttribute(gemm_mma_kernel, cudaFuncAttributeMaxDynamicSharedMemorySize, GEMM_SMEM);
    cudaFuncSetAttribute(flash_mma_kernel, cudaFuncAttributeMaxDynamicSharedMemorySize, FLASH_SMEM);

    // persistent side stream + events (created on first, uncaptured, call)
    static cudaStream_t s2 = nullptr;
    static cudaEvent_t evFork = nullptr, evLayer[Ll], evHead = nullptr;
    if (!s2) {
        cudaStreamCreateWithFlags(&s2, cudaStreamNonBlocking);
        cudaEventCreateWithFlags(&evFork, cudaEventDisableTiming);
        for (int l = 0; l < Ll; l++)
            cudaEventCreateWithFlags(&evLayer[l], cudaEventDisableTiming);
        cudaEventCreateWithFlags(&evHead, cudaEventDisableTiming);
    }

    // fork side stream from origin, then per-layer weight splits on s2
    cudaEventRecord(evFork, 0);
    cudaStreamWaitEvent(s2, evFork, 0);
    for (int l = 0; l < Ll; l++) {
        split_on(s2, in_proj_w  + (size_t)l * E3 * Ee, wq_hi + (size_t)l * E3 * Ee,
                 wq_lo + (size_t)l * E3 * Ee, E3 * Ee);
        split_on(s2, out_proj_w + (size_t)l * Ee * Ee, wo_hi + (size_t)l * Ee * Ee,
                 wo_lo + (size_t)l * Ee * Ee, Ee * Ee);
        split_on(s2, lin1_w     + (size_t)l * Ff * Ee, w1_hi + (size_t)l * Ff * Ee,
                 w1_lo + (size_t)l * Ff * Ee, Ff * Ee);
        split_on(s2, lin2_w     + (size_t)l * Ee * Ff, w2_hi + (size_t)l * Ee * Ff,
                 w2_lo + (size_t)l * Ee * Ff, Ee * Ff);
        cudaEventRecord(evLayer[l], s2);
    }
    head_split_kernel<<<(NVPAD * Ee / 4) / 256, 256, 0, s2>>>(gen_w, gw_hi, gw_lo);
    head_bias_kernel<<<2, 256, 0, s2>>>(gen_b, gbp);
    cudaEventRecord(evHead, s2);

    // embedding (runs concurrently with early splits)
    embed_kernel<<<(Tt * Ee / 2) / 256, 256>>>(seq, map1, map2, emb, pos_emb, x, x_hi, x_lo);

    const size_t TE = (size_t)Tt * Ee;
    for (int l = 0; l < Ll; l++) {
        cudaStreamWaitEvent(0, evLayer[l], 0);   // layer-l weights ready
        // qkv = x @ Wq^T + b -> hi/lo
        gemm_mma_kernel<<<dim3(E3 / 128, Tt / 128, 1), 256, GEMM_SMEM>>>(
            x_hi, x_lo, wq_hi + (size_t)l * E3 * Ee, wq_lo + (size_t)l * E3 * Ee,
            in_proj_b + (size_t)l * E3, nullptr, nullptr, qkv_hi, qkv_lo,
            Tt, Ee, Ee, 0, E3, E3);
        // attention -> ctx hi/lo (128-query CTAs)
        flash_mma_kernel<<<dim3(Ss / 128, Bb * Hh), 256, FLASH_SMEM>>>(
            qkv_hi, qkv_lo, dist_emb, seq, c_hi, c_lo);
        // tmp[z] = partial(ctx @ Wo^T); z0 += b + x   (split-K=2)
        gemm_mma_kernel<<<dim3(Ee / 128, Tt / 128, 2), 256, GEMM_SMEM>>>(
            c_hi, c_lo, wo_hi + (size_t)l * Ee * Ee, wo_lo + (size_t)l * Ee * Ee,
            out_proj_b + (size_t)l * Ee, x, tmpp, nullptr, nullptr,
            Tt, Ee, Ee / 2, 0, Ee, Ee);
        // x = LN(tmp0 + tmp1)
        add_ln_kernel<<<Tt, 256>>>(tmpp, tmpp + TE, ln1_w + (size_t)l * Ee, ln1_b + (size_t)l * Ee,
                                   x, x_hi, x_lo);
        // h = gelu(x @ W1^T + b) -> hi/lo
        gemm_mma_kernel<<<dim3(Ff / 128, Tt / 128, 1), 256, GEMM_SMEM>>>(
            x_hi, x_lo, w1_hi + (size_t)l * Ff * Ee, w1_lo + (size_t)l * Ff * Ee,
            lin1_b + (size_t)l * Ff, nullptr, nullptr, h_hi, h_lo,
            Tt, Ee, Ee, 1, Ff, Ff);
        // tmp[z] = partial(h @ W2^T); z0 += b + x   (split-K=2)
        gemm_mma_kernel<<<dim3(Ee / 128, Tt / 128, 2), 256, GEMM_SMEM>>>(
            h_hi, h_lo, w2_hi + (size_t)l * Ee * Ff, w2_lo + (size_t)l * Ee * Ff,
            lin2_b + (size_t)l * Ee, x, tmpp, nullptr, nullptr,
            Tt, Ff, Ff / 2, 0, Ee, Ee);
        // x = LN(tmp0 + tmp1)
        add_ln_kernel<<<Tt, 256>>>(tmpp, tmpp + TE, ln2_w + (size_t)l * Ee, ln2_b + (size_t)l * Ee,
                                   x, x_hi, x_lo);
    }

    // final norm -> fp32 + hi/lo
    add_ln_kernel<<<Tt, 256>>>(x, nullptr, fnorm_w, fnorm_b, finp, x_hi, x_lo);
    // logits = xn @ gen_w^T + gen_b (padded N=512, guarded to 400)
    cudaStreamWaitEvent(0, evHead, 0);
    gemm_mma_kernel<<<dim3(NVPAD / 128, Tt / 128, 1), 256, GEMM_SMEM>>>(
        x_hi, x_lo, gw_hi, gw_lo, gbp, nullptr, out, nullptr, nullptr,
        Tt, Ee, Ee, 0, Vv, Vv);
}